// round 1
// baseline (speedup 1.0000x reference)
#include <cuda_runtime.h>
#include <math.h>

typedef unsigned long long u64;

#define NMAX 50000
#define EMAX 640000

// Scratch (static __device__ arrays per allocation rules)
__device__ float g_x[(size_t)NMAX * 128];
__device__ float g_sums[(size_t)NMAX * 128];
__device__ float g_cnt[NMAX];

__device__ __forceinline__ float sp_act(float x) {
    // softplus(x) - log(2), numerically stable
    return fmaxf(x, 0.f) + log1pf(expf(-fabsf(x))) - 0.69314718055994531f;
}

// ---- packed fp32x2 helpers (sm_103a) ----
__device__ __forceinline__ u64 dup2(float a) {
    u64 r; asm("mov.b64 %0, {%1, %1};" : "=l"(r) : "f"(a)); return r;
}
__device__ __forceinline__ void ffma2(u64& d, u64 a, u64 b) {
    asm("fma.rn.f32x2 %0, %1, %2, %0;" : "+l"(d) : "l"(a), "l"(b));
}
__device__ __forceinline__ u64 pack2(float x, float y) {
    u64 r; asm("mov.b64 %0, {%1, %2};" : "=l"(r) : "f"(x), "f"(y)); return r;
}
__device__ __forceinline__ float2 unpack2(u64 v) {
    float2 r; asm("mov.b64 {%0, %1}, %2;" : "=f"(r.x), "=f"(r.y) : "l"(v)); return r;
}

// Per-thread 8x4 tile GEMM on SMEM operands.
// Thread (tr, tc) computes rows tr*8..tr*8+7, cols tc*4..tc*4+3.
// As: [rows][AS] row-major. Ws: [K][128] row-major.
template<int K, int AS>
__device__ __forceinline__ void mm_tile(const float* __restrict__ As,
                                        const float* __restrict__ Ws,
                                        int tr, int tc, u64 acc[8][2]) {
    const float* Arow = As + tr * 8 * AS;
    const float* Wp = Ws + tc * 4;
    #pragma unroll 4
    for (int k = 0; k < K; k += 4) {
        ulonglong2 t0 = *(const ulonglong2*)(Wp + (k + 0) * 128);
        ulonglong2 t1 = *(const ulonglong2*)(Wp + (k + 1) * 128);
        ulonglong2 t2 = *(const ulonglong2*)(Wp + (k + 2) * 128);
        ulonglong2 t3 = *(const ulonglong2*)(Wp + (k + 3) * 128);
        #pragma unroll
        for (int i = 0; i < 8; i++) {
            float4 a = *(const float4*)(Arow + i * AS + k);
            u64 a0 = dup2(a.x), a1 = dup2(a.y), a2 = dup2(a.z), a3 = dup2(a.w);
            ffma2(acc[i][0], a0, t0.x); ffma2(acc[i][1], a0, t0.y);
            ffma2(acc[i][0], a1, t1.x); ffma2(acc[i][1], a1, t1.y);
            ffma2(acc[i][0], a2, t2.x); ffma2(acc[i][1], a2, t2.y);
            ffma2(acc[i][0], a3, t3.x); ffma2(acc[i][1], a3, t3.y);
        }
    }
}

// ---------------- Kernel 1: x = node_fea @ W_aw1 (no bias) ----------------
__global__ __launch_bounds__(256) void gemm_x_kernel(const float* __restrict__ A,
                                                     const float* __restrict__ W, int N) {
    extern __shared__ float sm[];
    float* Ws = sm;                 // 128*128
    float* As = sm + 128 * 128;     // 64*128
    int tid = threadIdx.x;
    int r0 = blockIdx.x * 64;

    for (int i = tid; i < 128 * 32; i += 256) ((float4*)Ws)[i] = ((const float4*)W)[i];
    for (int i = tid; i < 64 * 32; i += 256) {
        int r = i >> 5, c = i & 31;
        int g = r0 + r;
        float4 z = {0.f, 0.f, 0.f, 0.f};
        ((float4*)As)[i] = (g < N) ? ((const float4*)A)[(size_t)g * 32 + c] : z;
    }
    __syncthreads();

    int tc = tid & 31, tr = tid >> 5;
    u64 acc[8][2];
    #pragma unroll
    for (int i = 0; i < 8; i++) { acc[i][0] = 0ull; acc[i][1] = 0ull; }
    mm_tile<128, 128>(As, Ws, tr, tc, acc);

    #pragma unroll
    for (int i = 0; i < 8; i++) {
        int g = r0 + tr * 8 + i;
        if (g < N) {
            float2 lo = unpack2(acc[i][0]), hi = unpack2(acc[i][1]);
            float4 v = {lo.x, lo.y, hi.x, hi.y};
            *(float4*)(g_x + (size_t)g * 128 + tc * 4) = v;
        }
    }
}

// ---------------- Kernel 2: fused edge pipeline ----------------
// h = sp(ef @ Wfg1 + b1); w = sp(h @ Wfg2 + b2); c = x[idx2]*w; atomic scatter into sums[idx1]
__global__ __launch_bounds__(256) void edge_kernel(const float* __restrict__ edge_fea,
                                                   const int* __restrict__ idx1,
                                                   const int* __restrict__ idx2,
                                                   const float* __restrict__ Wfg1,
                                                   const float* __restrict__ bfg1,
                                                   const float* __restrict__ Wfg2,
                                                   const float* __restrict__ bfg2, int E) {
    extern __shared__ float sm[];
    float* W1s = sm;                    // 64*128
    float* W2s = W1s + 64 * 128;        // 128*128
    float* efs = W2s + 128 * 128;       // 64*64
    float* hs  = efs + 64 * 64;         // 64*128
    float* b1s = hs + 64 * 128;         // 128
    float* b2s = b1s + 128;             // 128
    int* i1s = (int*)(b2s + 128);       // 64
    int* i2s = i1s + 64;                // 64

    int tid = threadIdx.x;
    int e0 = blockIdx.x * 64;

    for (int i = tid; i < 64 * 32; i += 256) ((float4*)W1s)[i] = ((const float4*)Wfg1)[i];
    for (int i = tid; i < 128 * 32; i += 256) ((float4*)W2s)[i] = ((const float4*)Wfg2)[i];
    if (tid < 128) { b1s[tid] = bfg1[tid]; b2s[tid] = bfg2[tid]; }
    for (int i = tid; i < 64 * 16; i += 256) {
        int r = i >> 4, c = i & 15;
        int g = e0 + r;
        float4 z = {0.f, 0.f, 0.f, 0.f};
        ((float4*)efs)[i] = (g < E) ? ((const float4*)edge_fea)[(size_t)g * 16 + c] : z;
    }
    if (tid < 64) {
        int g = e0 + tid;
        i1s[tid] = (g < E) ? idx1[g] : 0;
        i2s[tid] = (g < E) ? idx2[g] : 0;
    }
    __syncthreads();

    int tc = tid & 31, tr = tid >> 5;
    u64 acc[8][2];

    // Phase 1: h = sp(ef @ W1 + b1)
    {
        float4 b = *(const float4*)(b1s + tc * 4);
        u64 blo = pack2(b.x, b.y), bhi = pack2(b.z, b.w);
        #pragma unroll
        for (int i = 0; i < 8; i++) { acc[i][0] = blo; acc[i][1] = bhi; }
    }
    mm_tile<64, 64>(efs, W1s, tr, tc, acc);
    #pragma unroll
    for (int i = 0; i < 8; i++) {
        float2 lo = unpack2(acc[i][0]), hi = unpack2(acc[i][1]);
        float4 v = {sp_act(lo.x), sp_act(lo.y), sp_act(hi.x), sp_act(hi.y)};
        *(float4*)(hs + (tr * 8 + i) * 128 + tc * 4) = v;
    }
    __syncthreads();

    // Phase 2: w = sp(h @ W2 + b2)
    {
        float4 b = *(const float4*)(b2s + tc * 4);
        u64 blo = pack2(b.x, b.y), bhi = pack2(b.z, b.w);
        #pragma unroll
        for (int i = 0; i < 8; i++) { acc[i][0] = blo; acc[i][1] = bhi; }
    }
    mm_tile<128, 128>(hs, W2s, tr, tc, acc);

    // Phase 3: gather-multiply + scatter
    #pragma unroll
    for (int i = 0; i < 8; i++) {
        int r = tr * 8 + i;
        int g = e0 + r;
        if (g < E) {
            int n1 = i1s[r], n2 = i2s[r];
            float2 lo = unpack2(acc[i][0]), hi = unpack2(acc[i][1]);
            float4 xv = *(const float4*)(g_x + (size_t)n2 * 128 + tc * 4);
            float* dst = g_sums + (size_t)n1 * 128 + tc * 4;
            atomicAdd(dst + 0, sp_act(lo.x) * xv.x);
            atomicAdd(dst + 1, sp_act(lo.y) * xv.y);
            atomicAdd(dst + 2, sp_act(hi.x) * xv.z);
            atomicAdd(dst + 3, sp_act(hi.y) * xv.w);
            if (tc == 0) atomicAdd(&g_cnt[n1], 1.0f);
        }
    }
}

// ---------------- Kernel 3: node epilogue ----------------
// mean = sums / max(cnt,1); h = sp(mean@W2 + b2); out = node_fea + h@W3 + b3
__global__ __launch_bounds__(256) void node_kernel(const float* __restrict__ node_fea,
                                                   const float* __restrict__ Waw2,
                                                   const float* __restrict__ baw2,
                                                   const float* __restrict__ Waw3,
                                                   const float* __restrict__ baw3,
                                                   float* __restrict__ out, int N) {
    extern __shared__ float sm[];
    float* W2s = sm;                    // 128*128
    float* W3s = W2s + 128 * 128;       // 128*128
    float* As  = W3s + 128 * 128;       // 64*128 (mean, later reused for h)
    float* b2s = As + 64 * 128;         // 128
    float* b3s = b2s + 128;             // 128
    float* cs  = b3s + 128;             // 64

    int tid = threadIdx.x;
    int r0 = blockIdx.x * 64;

    for (int i = tid; i < 128 * 32; i += 256) ((float4*)W2s)[i] = ((const float4*)Waw2)[i];
    for (int i = tid; i < 128 * 32; i += 256) ((float4*)W3s)[i] = ((const float4*)Waw3)[i];
    if (tid < 128) { b2s[tid] = baw2[tid]; b3s[tid] = baw3[tid]; }
    if (tid < 64) {
        int g = r0 + tid;
        cs[tid] = (g < N) ? fmaxf(g_cnt[g], 1.f) : 1.f;
    }
    __syncthreads();
    for (int i = tid; i < 64 * 32; i += 256) {
        int r = i >> 5, c = i & 31;
        int g = r0 + r;
        float4 v = {0.f, 0.f, 0.f, 0.f};
        if (g < N) v = ((const float4*)g_sums)[(size_t)g * 32 + c];
        float inv = 1.f / cs[r];
        v.x *= inv; v.y *= inv; v.z *= inv; v.w *= inv;
        ((float4*)As)[i] = v;
    }
    __syncthreads();

    int tc = tid & 31, tr = tid >> 5;
    u64 acc[8][2];

    // Phase 1: h = sp(mean @ W2 + b2)
    {
        float4 b = *(const float4*)(b2s + tc * 4);
        u64 blo = pack2(b.x, b.y), bhi = pack2(b.z, b.w);
        #pragma unroll
        for (int i = 0; i < 8; i++) { acc[i][0] = blo; acc[i][1] = bhi; }
    }
    mm_tile<128, 128>(As, W2s, tr, tc, acc);
    float4 hv[8];
    #pragma unroll
    for (int i = 0; i < 8; i++) {
        float2 lo = unpack2(acc[i][0]), hi = unpack2(acc[i][1]);
        hv[i] = make_float4(sp_act(lo.x), sp_act(lo.y), sp_act(hi.x), sp_act(hi.y));
    }
    __syncthreads();  // all reads of As done before overwrite
    #pragma unroll
    for (int i = 0; i < 8; i++)
        *(float4*)(As + (tr * 8 + i) * 128 + tc * 4) = hv[i];
    __syncthreads();

    // Phase 2: out = node_fea + h @ W3 + b3
    {
        float4 b = *(const float4*)(b3s + tc * 4);
        u64 blo = pack2(b.x, b.y), bhi = pack2(b.z, b.w);
        #pragma unroll
        for (int i = 0; i < 8; i++) { acc[i][0] = blo; acc[i][1] = bhi; }
    }
    mm_tile<128, 128>(As, W3s, tr, tc, acc);

    #pragma unroll
    for (int i = 0; i < 8; i++) {
        int g = r0 + tr * 8 + i;
        if (g < N) {
            float2 lo = unpack2(acc[i][0]), hi = unpack2(acc[i][1]);
            float4 nf = *(const float4*)(node_fea + (size_t)g * 128 + tc * 4);
            float4 v = {nf.x + lo.x, nf.y + lo.y, nf.z + hi.x, nf.w + hi.y};
            *(float4*)(out + (size_t)g * 128 + tc * 4) = v;
        }
    }
}

extern "C" void kernel_launch(void* const* d_in, const int* in_sizes, int n_in,
                              void* d_out, int out_size) {
    const float* node_fea = (const float*)d_in[0];
    const int*   idx1     = (const int*)d_in[1];
    const int*   idx2     = (const int*)d_in[2];
    const float* edge_fea = (const float*)d_in[3];
    const float* W_aw1    = (const float*)d_in[4];
    const float* W_fg1    = (const float*)d_in[5];
    const float* b_fg1    = (const float*)d_in[6];
    const float* W_fg2    = (const float*)d_in[7];
    const float* b_fg2    = (const float*)d_in[8];
    const float* W_aw2    = (const float*)d_in[9];
    const float* b_aw2    = (const float*)d_in[10];
    const float* W_aw3    = (const float*)d_in[11];
    const float* b_aw3    = (const float*)d_in[12];

    int N = in_sizes[0] / 128;
    int E = in_sizes[1];
    float* out = (float*)d_out;

    void *p_sums, *p_cnt;
    cudaGetSymbolAddress(&p_sums, g_sums);
    cudaGetSymbolAddress(&p_cnt, g_cnt);
    cudaMemsetAsync(p_sums, 0, (size_t)N * 128 * sizeof(float));
    cudaMemsetAsync(p_cnt, 0, (size_t)N * sizeof(float));

    int smemX = (128 * 128 + 64 * 128) * 4;
    int smemE = (64 * 128 + 128 * 128 + 64 * 64 + 64 * 128 + 128 + 128) * 4 + 128 * 4;
    int smemN = (128 * 128 * 2 + 64 * 128 + 128 + 128 + 64) * 4;
    cudaFuncSetAttribute(gemm_x_kernel, cudaFuncAttributeMaxDynamicSharedMemorySize, smemX);
    cudaFuncSetAttribute(edge_kernel, cudaFuncAttributeMaxDynamicSharedMemorySize, smemE);
    cudaFuncSetAttribute(node_kernel, cudaFuncAttributeMaxDynamicSharedMemorySize, smemN);

    int gbN = (N + 63) / 64;
    int gbE = (E + 63) / 64;

    gemm_x_kernel<<<gbN, 256, smemX>>>(node_fea, W_aw1, N);
    edge_kernel<<<gbE, 256, smemE>>>(edge_fea, idx1, idx2, W_fg1, b_fg1, W_fg2, b_fg2, E);
    node_kernel<<<gbN, 256, smemN>>>(node_fea, W_aw2, b_aw2, W_aw3, b_aw3, out, N);
}

// round 3
// speedup vs baseline: 1.9088x; 1.9088x over previous
#include <cuda_runtime.h>
#include <math.h>
#include <stdint.h>

typedef unsigned long long u64;

#define NMAX 50000
#define EMAX 640000

// Scratch (static __device__ arrays per allocation rules)
__device__ float g_x[(size_t)NMAX * 128];
__device__ float g_sums[(size_t)NMAX * 128];
__device__ float g_cnt[NMAX];
__device__ float g_w1t[128 * 68];     // W_fg1^T [n][k], k<64, stride 68, tf32-rounded
__device__ float g_w2t[128 * 132];    // W_fg2^T [n][k], k<128, stride 132, tf32-rounded

__device__ __forceinline__ float sp_act(float x) {
    return fmaxf(x, 0.f) + log1pf(expf(-fabsf(x))) - 0.69314718055994531f;
}
// fast softplus - ln2 via MUFU (rel err ~1e-6)
__device__ __forceinline__ float sp_fast(float x) {
    float t = __expf(-fabsf(x));
    return fmaxf(x, 0.f) + __logf(1.f + t) - 0.69314718055994531f;
}
__device__ __forceinline__ float tf32r(float x) {
    uint32_t u;
    asm("cvt.rna.tf32.f32 %0, %1;" : "=r"(u) : "f"(x));
    return __uint_as_float(u);
}

// ---- packed fp32x2 helpers (node-side fp32 SIMT kernels) ----
__device__ __forceinline__ u64 dup2(float a) {
    u64 r; asm("mov.b64 %0, {%1, %1};" : "=l"(r) : "f"(a)); return r;
}
__device__ __forceinline__ void ffma2(u64& d, u64 a, u64 b) {
    asm("fma.rn.f32x2 %0, %1, %2, %0;" : "+l"(d) : "l"(a), "l"(b));
}
__device__ __forceinline__ u64 pack2(float x, float y) {
    u64 r; asm("mov.b64 %0, {%1, %2};" : "=l"(r) : "f"(x), "f"(y)); return r;
}
__device__ __forceinline__ float2 unpack2(u64 v) {
    float2 r; asm("mov.b64 {%0, %1}, %2;" : "=f"(r.x), "=f"(r.y) : "l"(v)); return r;
}

// ---- tf32 mma.sync (sm_80-era path, valid on plain sm_103 target) ----
__device__ __forceinline__ void mma8(float d[4], const uint32_t a[4], uint32_t b0, uint32_t b1) {
    asm("mma.sync.aligned.m16n8k8.row.col.f32.tf32.tf32.f32 "
        "{%0,%1,%2,%3}, {%4,%5,%6,%7}, {%8,%9}, {%0,%1,%2,%3};"
        : "+f"(d[0]), "+f"(d[1]), "+f"(d[2]), "+f"(d[3])
        : "r"(a[0]), "r"(a[1]), "r"(a[2]), "r"(a[3]), "r"(b0), "r"(b1));
}

// Warp-level GEMM: acc[2][8][4] covers a 32(m) x 64(n) warp tile.
// As: [128][SA] row-major (m,k). Bs: [128][SB] row-major (n,k).
template<int K, int SA, int SB>
__device__ __forceinline__ void mma_gemm(const float* As, const float* Bs,
                                         int mw, int nw, int g, int q,
                                         float acc[2][8][4]) {
    #pragma unroll
    for (int kk = 0; kk < K; kk += 8) {
        uint32_t a[2][4];
        #pragma unroll
        for (int mt = 0; mt < 2; mt++) {
            const float* Ar = As + (mw * 32 + mt * 16 + g) * SA + kk + q;
            a[mt][0] = __float_as_uint(Ar[0]);
            a[mt][2] = __float_as_uint(Ar[4]);
            a[mt][1] = __float_as_uint(Ar[8 * SA]);
            a[mt][3] = __float_as_uint(Ar[8 * SA + 4]);
        }
        #pragma unroll
        for (int nt = 0; nt < 8; nt++) {
            const float* Br = Bs + (nw * 64 + nt * 8 + g) * SB + kk + q;
            uint32_t b0 = __float_as_uint(Br[0]);
            uint32_t b1 = __float_as_uint(Br[4]);
            mma8(acc[0][nt], a[0], b0, b1);
            mma8(acc[1][nt], a[1], b0, b1);
        }
    }
}

// ------------- prep: transpose + tf32-round weights into [n][k] images -------------
__global__ void prep_weights(const float* __restrict__ W1, const float* __restrict__ W2) {
    int t = blockIdx.x * blockDim.x + threadIdx.x;
    int stride = blockDim.x * gridDim.x;
    for (int i = t; i < 64 * 128; i += stride) {
        int k = i >> 7, n = i & 127;
        g_w1t[n * 68 + k] = tf32r(W1[i]);
    }
    for (int i = t; i < 128 * 128; i += stride) {
        int k = i >> 7, n = i & 127;
        g_w2t[n * 132 + k] = tf32r(W2[i]);
    }
}

// ---------------- Kernel 1: x = node_fea @ W_aw1 (no bias), fp32 ----------------
__global__ __launch_bounds__(256) void gemm_x_kernel(const float* __restrict__ A,
                                                     const float* __restrict__ W, int N) {
    extern __shared__ float sm[];
    float* Ws = sm;
    float* As = sm + 128 * 128;
    int tid = threadIdx.x;
    int r0 = blockIdx.x * 64;

    for (int i = tid; i < 128 * 32; i += 256) ((float4*)Ws)[i] = ((const float4*)W)[i];
    for (int i = tid; i < 64 * 32; i += 256) {
        int r = i >> 5, c = i & 31;
        int gg = r0 + r;
        float4 z = {0.f, 0.f, 0.f, 0.f};
        ((float4*)As)[i] = (gg < N) ? ((const float4*)A)[(size_t)gg * 32 + c] : z;
    }
    __syncthreads();

    int tc = tid & 31, tr = tid >> 5;
    u64 acc[8][2];
    #pragma unroll
    for (int i = 0; i < 8; i++) { acc[i][0] = 0ull; acc[i][1] = 0ull; }
    {
        const float* Arow = As + tr * 8 * 128;
        const float* Wp = Ws + tc * 4;
        #pragma unroll 4
        for (int k = 0; k < 128; k += 4) {
            ulonglong2 t0 = *(const ulonglong2*)(Wp + (k + 0) * 128);
            ulonglong2 t1 = *(const ulonglong2*)(Wp + (k + 1) * 128);
            ulonglong2 t2 = *(const ulonglong2*)(Wp + (k + 2) * 128);
            ulonglong2 t3 = *(const ulonglong2*)(Wp + (k + 3) * 128);
            #pragma unroll
            for (int i = 0; i < 8; i++) {
                float4 a = *(const float4*)(Arow + i * 128 + k);
                u64 a0 = dup2(a.x), a1 = dup2(a.y), a2 = dup2(a.z), a3 = dup2(a.w);
                ffma2(acc[i][0], a0, t0.x); ffma2(acc[i][1], a0, t0.y);
                ffma2(acc[i][0], a1, t1.x); ffma2(acc[i][1], a1, t1.y);
                ffma2(acc[i][0], a2, t2.x); ffma2(acc[i][1], a2, t2.y);
                ffma2(acc[i][0], a3, t3.x); ffma2(acc[i][1], a3, t3.y);
            }
        }
    }
    #pragma unroll
    for (int i = 0; i < 8; i++) {
        int gg = r0 + tr * 8 + i;
        if (gg < N) {
            float2 lo = unpack2(acc[i][0]), hi = unpack2(acc[i][1]);
            float4 v = {lo.x, lo.y, hi.x, hi.y};
            *(float4*)(g_x + (size_t)gg * 128 + tc * 4) = v;
        }
    }
}

// ---------------- Kernel 2: persistent tf32-MMA fused edge pipeline ----------------
// SMEM floats: W1t[128*68] W2t[128*132] A1[128*68] A2[128*132] b1s[128] b2s[128] idx[256]
#define EDGE_SMEM_F (128*68 + 128*132 + 128*68 + 128*132 + 128 + 128 + 256)

__global__ __launch_bounds__(256) void edge_mma_kernel(const float* __restrict__ ef,
                                                       const int* __restrict__ idx1,
                                                       const int* __restrict__ idx2,
                                                       const float* __restrict__ b1,
                                                       const float* __restrict__ b2,
                                                       int E, int ntiles) {
    extern __shared__ float sm[];
    float* W1t = sm;
    float* W2t = W1t + 128 * 68;
    float* A1  = W2t + 128 * 132;
    float* A2  = A1 + 128 * 68;
    float* b1s = A2 + 128 * 132;
    float* b2s = b1s + 128;
    int* i1s = (int*)(b2s + 128);
    int* i2s = i1s + 128;

    int tid = threadIdx.x, wid = tid >> 5, lane = tid & 31;
    int g = lane >> 2, q = lane & 3;
    int mw = wid & 3, nw = wid >> 2;

    // weights: load once per block (persistent)
    for (int i = tid; i < 128 * 68 / 4; i += 256) ((float4*)W1t)[i] = ((const float4*)g_w1t)[i];
    for (int i = tid; i < 128 * 132 / 4; i += 256) ((float4*)W2t)[i] = ((const float4*)g_w2t)[i];
    if (tid < 128) { b1s[tid] = b1[tid]; b2s[tid] = b2[tid]; }

    for (int t = blockIdx.x; t < ntiles; t += gridDim.x) {
        int e0 = t * 128;
        __syncthreads();
        // fill A1 (tf32-rounded) + indices
        for (int i = tid; i < 2048; i += 256) {
            int m = i >> 4, qq = i & 15;
            int e = e0 + m;
            float4 v = {0.f, 0.f, 0.f, 0.f};
            if (e < E) v = ((const float4*)ef)[(size_t)e * 16 + qq];
            float* dst = A1 + m * 68 + qq * 4;
            dst[0] = tf32r(v.x); dst[1] = tf32r(v.y); dst[2] = tf32r(v.z); dst[3] = tf32r(v.w);
        }
        if (tid < 128) {
            int e = e0 + tid;
            i1s[tid] = (e < E) ? idx1[e] : 0;
            i2s[tid] = (e < E) ? idx2[e] : 0;
        }
        __syncthreads();

        // ---- GEMM1: h = A1 @ W1^T  (K=64) ----
        float acc[2][8][4];
        #pragma unroll
        for (int a = 0; a < 2; a++)
            #pragma unroll
            for (int b = 0; b < 8; b++)
                #pragma unroll
                for (int c = 0; c < 4; c++) acc[a][b][c] = 0.f;
        mma_gemm<64, 68, 68>(A1, W1t, mw, nw, g, q, acc);

        // ---- epilogue 1: A2 = tf32(sp(h + b1)) ----
        #pragma unroll
        for (int mt = 0; mt < 2; mt++) {
            int r = mw * 32 + mt * 16 + g;
            #pragma unroll
            for (int nt = 0; nt < 8; nt++) {
                int c0 = nw * 64 + nt * 8 + 2 * q;
                float2 bb = *(const float2*)(b1s + c0);
                float2 v0, v1;
                v0.x = tf32r(sp_fast(acc[mt][nt][0] + bb.x));
                v0.y = tf32r(sp_fast(acc[mt][nt][1] + bb.y));
                v1.x = tf32r(sp_fast(acc[mt][nt][2] + bb.x));
                v1.y = tf32r(sp_fast(acc[mt][nt][3] + bb.y));
                *(float2*)(A2 + r * 132 + c0) = v0;
                *(float2*)(A2 + (r + 8) * 132 + c0) = v1;
            }
        }
        __syncthreads();

        // ---- GEMM2: W = A2 @ W2^T  (K=128) ----
        #pragma unroll
        for (int a = 0; a < 2; a++)
            #pragma unroll
            for (int b = 0; b < 8; b++)
                #pragma unroll
                for (int c = 0; c < 4; c++) acc[a][b][c] = 0.f;
        mma_gemm<128, 132, 132>(A2, W2t, mw, nw, g, q, acc);

        // ---- epilogue 2: w=sp(acc+b2); scatter w * x[idx2] into sums[idx1] ----
        #pragma unroll
        for (int mt = 0; mt < 2; mt++) {
            #pragma unroll
            for (int rr = 0; rr < 2; rr++) {
                int r = mw * 32 + mt * 16 + g + rr * 8;
                int e = e0 + r;
                if (e < E) {
                    int n1 = i1s[r], n2 = i2s[r];
                    const float* xr = g_x + (size_t)n2 * 128;
                    float* sr = g_sums + (size_t)n1 * 128;
                    int ci = rr * 2;
                    #pragma unroll
                    for (int nt = 0; nt < 8; nt++) {
                        int c0 = nw * 64 + nt * 8 + 2 * q;
                        float2 xv = *(const float2*)(xr + c0);
                        float w0 = sp_fast(acc[mt][nt][ci + 0] + b2s[c0]);
                        float w1 = sp_fast(acc[mt][nt][ci + 1] + b2s[c0 + 1]);
                        float a0 = w0 * xv.x, a1 = w1 * xv.y;
                        asm volatile("red.global.add.v2.f32 [%0], {%1,%2};"
                                     :: "l"(sr + c0), "f"(a0), "f"(a1) : "memory");
                    }
                    if (q == 0 && nw == 0) atomicAdd(&g_cnt[n1], 1.0f);
                }
            }
        }
    }
}

// ---------------- Kernel 3: node epilogue (fp32) ----------------
__global__ __launch_bounds__(256) void node_kernel(const float* __restrict__ node_fea,
                                                   const float* __restrict__ Waw2,
                                                   const float* __restrict__ baw2,
                                                   const float* __restrict__ Waw3,
                                                   const float* __restrict__ baw3,
                                                   float* __restrict__ out, int N) {
    extern __shared__ float sm[];
    float* W2s = sm;
    float* W3s = W2s + 128 * 128;
    float* As  = W3s + 128 * 128;
    float* b2s = As + 64 * 128;
    float* b3s = b2s + 128;
    float* cs  = b3s + 128;

    int tid = threadIdx.x;
    int r0 = blockIdx.x * 64;

    for (int i = tid; i < 128 * 32; i += 256) ((float4*)W2s)[i] = ((const float4*)Waw2)[i];
    for (int i = tid; i < 128 * 32; i += 256) ((float4*)W3s)[i] = ((const float4*)Waw3)[i];
    if (tid < 128) { b2s[tid] = baw2[tid]; b3s[tid] = baw3[tid]; }
    if (tid < 64) {
        int gg = r0 + tid;
        cs[tid] = (gg < N) ? fmaxf(g_cnt[gg], 1.f) : 1.f;
    }
    __syncthreads();
    for (int i = tid; i < 64 * 32; i += 256) {
        int r = i >> 5, c = i & 31;
        int gg = r0 + r;
        float4 v = {0.f, 0.f, 0.f, 0.f};
        if (gg < N) v = ((const float4*)g_sums)[(size_t)gg * 32 + c];
        float inv = 1.f / cs[r];
        v.x *= inv; v.y *= inv; v.z *= inv; v.w *= inv;
        ((float4*)As)[i] = v;
    }
    __syncthreads();

    int tc = tid & 31, tr = tid >> 5;
    u64 acc[8][2];

    {
        float4 b = *(const float4*)(b2s + tc * 4);
        u64 blo = pack2(b.x, b.y), bhi = pack2(b.z, b.w);
        #pragma unroll
        for (int i = 0; i < 8; i++) { acc[i][0] = blo; acc[i][1] = bhi; }
    }
    {
        const float* Arow = As + tr * 8 * 128;
        const float* Wp = W2s + tc * 4;
        #pragma unroll 4
        for (int k = 0; k < 128; k += 4) {
            ulonglong2 t0 = *(const ulonglong2*)(Wp + (k + 0) * 128);
            ulonglong2 t1 = *(const ulonglong2*)(Wp + (k + 1) * 128);
            ulonglong2 t2 = *(const ulonglong2*)(Wp + (k + 2) * 128);
            ulonglong2 t3 = *(const ulonglong2*)(Wp + (k + 3) * 128);
            #pragma unroll
            for (int i = 0; i < 8; i++) {
                float4 a = *(const float4*)(Arow + i * 128 + k);
                u64 a0 = dup2(a.x), a1 = dup2(a.y), a2 = dup2(a.z), a3 = dup2(a.w);
                ffma2(acc[i][0], a0, t0.x); ffma2(acc[i][1], a0, t0.y);
                ffma2(acc[i][0], a1, t1.x); ffma2(acc[i][1], a1, t1.y);
                ffma2(acc[i][0], a2, t2.x); ffma2(acc[i][1], a2, t2.y);
                ffma2(acc[i][0], a3, t3.x); ffma2(acc[i][1], a3, t3.y);
            }
        }
    }
    float4 hv[8];
    #pragma unroll
    for (int i = 0; i < 8; i++) {
        float2 lo = unpack2(acc[i][0]), hi = unpack2(acc[i][1]);
        hv[i] = make_float4(sp_act(lo.x), sp_act(lo.y), sp_act(hi.x), sp_act(hi.y));
    }
    __syncthreads();
    #pragma unroll
    for (int i = 0; i < 8; i++)
        *(float4*)(As + (tr * 8 + i) * 128 + tc * 4) = hv[i];
    __syncthreads();

    {
        float4 b = *(const float4*)(b3s + tc * 4);
        u64 blo = pack2(b.x, b.y), bhi = pack2(b.z, b.w);
        #pragma unroll
        for (int i = 0; i < 8; i++) { acc[i][0] = blo; acc[i][1] = bhi; }
    }
    {
        const float* Arow = As + tr * 8 * 128;
        const float* Wp = W3s + tc * 4;
        #pragma unroll 4
        for (int k = 0; k < 128; k += 4) {
            ulonglong2 t0 = *(const ulonglong2*)(Wp + (k + 0) * 128);
            ulonglong2 t1 = *(const ulonglong2*)(Wp + (k + 1) * 128);
            ulonglong2 t2 = *(const ulonglong2*)(Wp + (k + 2) * 128);
            ulonglong2 t3 = *(const ulonglong2*)(Wp + (k + 3) * 128);
            #pragma unroll
            for (int i = 0; i < 8; i++) {
                float4 a = *(const float4*)(Arow + i * 128 + k);
                u64 a0 = dup2(a.x), a1 = dup2(a.y), a2 = dup2(a.z), a3 = dup2(a.w);
                ffma2(acc[i][0], a0, t0.x); ffma2(acc[i][1], a0, t0.y);
                ffma2(acc[i][0], a1, t1.x); ffma2(acc[i][1], a1, t1.y);
                ffma2(acc[i][0], a2, t2.x); ffma2(acc[i][1], a2, t2.y);
                ffma2(acc[i][0], a3, t3.x); ffma2(acc[i][1], a3, t3.y);
            }
        }
    }

    #pragma unroll
    for (int i = 0; i < 8; i++) {
        int gg = r0 + tr * 8 + i;
        if (gg < N) {
            float2 lo = unpack2(acc[i][0]), hi = unpack2(acc[i][1]);
            float4 nf = *(const float4*)(node_fea + (size_t)gg * 128 + tc * 4);
            float4 v = {nf.x + lo.x, nf.y + lo.y, nf.z + hi.x, nf.w + hi.y};
            *(float4*)(out + (size_t)gg * 128 + tc * 4) = v;
        }
    }
}

extern "C" void kernel_launch(void* const* d_in, const int* in_sizes, int n_in,
                              void* d_out, int out_size) {
    const float* node_fea = (const float*)d_in[0];
    const int*   idx1     = (const int*)d_in[1];
    const int*   idx2     = (const int*)d_in[2];
    const float* edge_fea = (const float*)d_in[3];
    const float* W_aw1    = (const float*)d_in[4];
    const float* W_fg1    = (const float*)d_in[5];
    const float* b_fg1    = (const float*)d_in[6];
    const float* W_fg2    = (const float*)d_in[7];
    const float* b_fg2    = (const float*)d_in[8];
    const float* W_aw2    = (const float*)d_in[9];
    const float* b_aw2    = (const float*)d_in[10];
    const float* W_aw3    = (const float*)d_in[11];
    const float* b_aw3    = (const float*)d_in[12];

    int N = in_sizes[0] / 128;
    int E = in_sizes[1];
    float* out = (float*)d_out;

    void *p_sums, *p_cnt;
    cudaGetSymbolAddress(&p_sums, g_sums);
    cudaGetSymbolAddress(&p_cnt, g_cnt);
    cudaMemsetAsync(p_sums, 0, (size_t)N * 128 * sizeof(float));
    cudaMemsetAsync(p_cnt, 0, (size_t)N * sizeof(float));

    int smemX = (128 * 128 + 64 * 128) * 4;
    int smemE = EDGE_SMEM_F * 4;
    int smemN = (128 * 128 * 2 + 64 * 128 + 128 + 128 + 64) * 4;
    cudaFuncSetAttribute(gemm_x_kernel, cudaFuncAttributeMaxDynamicSharedMemorySize, smemX);
    cudaFuncSetAttribute(edge_mma_kernel, cudaFuncAttributeMaxDynamicSharedMemorySize, smemE);
    cudaFuncSetAttribute(node_kernel, cudaFuncAttributeMaxDynamicSharedMemorySize, smemN);

    int gbN = (N + 63) / 64;
    int ntiles = (E + 127) / 128;
    int gbE = ntiles < 148 ? ntiles : 148;

    prep_weights<<<32, 256>>>(W_fg1, W_fg2);
    gemm_x_kernel<<<gbN, 256, smemX>>>(node_fea, W_aw1, N);
    edge_mma_kernel<<<gbE, 256, smemE>>>(edge_fea, idx1, idx2, b_fg1, b_fg2, E, ntiles);
    node_kernel<<<gbN, 256, smemN>>>(node_fea, W_aw2, b_aw2, W_aw3, b_aw3, out, N);
}

// round 4
// speedup vs baseline: 2.8497x; 1.4930x over previous
#include <cuda_runtime.h>
#include <math.h>
#include <stdint.h>

typedef unsigned long long u64;

#define NMAX 50000
#define EMAX 640000

// Scratch (static __device__ arrays per allocation rules)
__device__ float g_x[(size_t)NMAX * 128];
__device__ float g_sums[(size_t)NMAX * 128];
__device__ float g_cnt[NMAX];
__device__ float g_w1t[128 * 68];      // W_fg1^T  [n][k], k<64,  stride 68,  tf32
__device__ float g_w2t[128 * 132];     // W_fg2^T  [n][k], k<128, stride 132, tf32
__device__ float g_waw1t[128 * 132];   // W_aw1^T
__device__ float g_waw2t[128 * 132];   // W_aw2^T
__device__ float g_waw3t[128 * 132];   // W_aw3^T

// fast softplus - ln2 via MUFU (rel err ~1e-6)
__device__ __forceinline__ float sp_fast(float x) {
    float t = __expf(-fabsf(x));
    return fmaxf(x, 0.f) + __logf(1.f + t) - 0.69314718055994531f;
}
__device__ __forceinline__ float tf32r(float x) {
    uint32_t u;
    asm("cvt.rna.tf32.f32 %0, %1;" : "=r"(u) : "f"(x));
    return __uint_as_float(u);
}

// ---- tf32 mma.sync m16n8k8 ----
__device__ __forceinline__ void mma8(float d[4], const uint32_t a[4], uint32_t b0, uint32_t b1) {
    asm("mma.sync.aligned.m16n8k8.row.col.f32.tf32.tf32.f32 "
        "{%0,%1,%2,%3}, {%4,%5,%6,%7}, {%8,%9}, {%0,%1,%2,%3};"
        : "+f"(d[0]), "+f"(d[1]), "+f"(d[2]), "+f"(d[3])
        : "r"(a[0]), "r"(a[1]), "r"(a[2]), "r"(a[3]), "r"(b0), "r"(b1));
}

__device__ __forceinline__ void zero_acc(float acc[2][8][4]) {
    #pragma unroll
    for (int a = 0; a < 2; a++)
        #pragma unroll
        for (int b = 0; b < 8; b++)
            #pragma unroll
            for (int c = 0; c < 4; c++) acc[a][b][c] = 0.f;
}

// Warp-level GEMM: acc[2][8][4] covers a 32(m) x 64(n) warp tile.
// As: [128][SA] row-major (m,k). Bs: [128][SB] row-major (n,k).
template<int K, int SA, int SB>
__device__ __forceinline__ void mma_gemm(const float* As, const float* Bs,
                                         int mw, int nw, int g, int q,
                                         float acc[2][8][4]) {
    #pragma unroll
    for (int kk = 0; kk < K; kk += 8) {
        uint32_t a[2][4];
        #pragma unroll
        for (int mt = 0; mt < 2; mt++) {
            const float* Ar = As + (mw * 32 + mt * 16 + g) * SA + kk + q;
            a[mt][0] = __float_as_uint(Ar[0]);
            a[mt][2] = __float_as_uint(Ar[4]);
            a[mt][1] = __float_as_uint(Ar[8 * SA]);
            a[mt][3] = __float_as_uint(Ar[8 * SA + 4]);
        }
        #pragma unroll
        for (int nt = 0; nt < 8; nt++) {
            const float* Br = Bs + (nw * 64 + nt * 8 + g) * SB + kk + q;
            uint32_t b0 = __float_as_uint(Br[0]);
            uint32_t b1 = __float_as_uint(Br[4]);
            mma8(acc[0][nt], a[0], b0, b1);
            mma8(acc[1][nt], a[1], b0, b1);
        }
    }
}

// ------------- prep: transpose + tf32-round all weights -------------
__global__ void prep_weights(const float* __restrict__ W1, const float* __restrict__ W2,
                             const float* __restrict__ Wa1, const float* __restrict__ Wa2,
                             const float* __restrict__ Wa3) {
    int t = blockIdx.x * blockDim.x + threadIdx.x;
    int stride = blockDim.x * gridDim.x;
    for (int i = t; i < 64 * 128; i += stride) {
        int k = i >> 7, n = i & 127;
        g_w1t[n * 68 + k] = tf32r(W1[i]);
    }
    for (int i = t; i < 128 * 128; i += stride) {
        int k = i >> 7, n = i & 127;
        g_w2t[n * 132 + k] = tf32r(W2[i]);
        g_waw1t[n * 132 + k] = tf32r(Wa1[i]);
        g_waw2t[n * 132 + k] = tf32r(Wa2[i]);
        g_waw3t[n * 132 + k] = tf32r(Wa3[i]);
    }
}

// ---------------- Kernel 1: x = node_fea @ W_aw1 (tf32 MMA, persistent) ----------------
#define XK_SMEM ((128 * 132 + 128 * 132) * 4)
__global__ __launch_bounds__(256) void gemm_x_mma(const float* __restrict__ A,
                                                  int N, int ntiles) {
    extern __shared__ float sm[];
    float* Wt = sm;                    // 128*132
    float* As = Wt + 128 * 132;        // 128*132
    int tid = threadIdx.x, wid = tid >> 5, lane = tid & 31;
    int g = lane >> 2, q = lane & 3;
    int mw = wid & 3, nw = wid >> 2;

    for (int i = tid; i < 128 * 132 / 4; i += 256) ((float4*)Wt)[i] = ((const float4*)g_waw1t)[i];

    for (int t = blockIdx.x; t < ntiles; t += gridDim.x) {
        int r0 = t * 128;
        for (int c = 0; c < 16; c++) {
            int ci = c * 256 + tid;
            int m = ci >> 5, qq = ci & 31;
            int r = r0 + m;
            float4 v = {0.f, 0.f, 0.f, 0.f};
            if (r < N) v = ((const float4*)A)[(size_t)r * 32 + qq];
            float* dst = As + m * 132 + qq * 4;
            dst[0] = tf32r(v.x); dst[1] = tf32r(v.y); dst[2] = tf32r(v.z); dst[3] = tf32r(v.w);
        }
        __syncthreads();
        float acc[2][8][4];
        zero_acc(acc);
        mma_gemm<128, 132, 132>(As, Wt, mw, nw, g, q, acc);
        #pragma unroll
        for (int mt = 0; mt < 2; mt++) {
            int rlo = r0 + mw * 32 + mt * 16 + g, rhi = rlo + 8;
            #pragma unroll
            for (int nt = 0; nt < 8; nt++) {
                int c0 = nw * 64 + nt * 8 + 2 * q;
                if (rlo < N) *(float2*)(g_x + (size_t)rlo * 128 + c0) = make_float2(acc[mt][nt][0], acc[mt][nt][1]);
                if (rhi < N) *(float2*)(g_x + (size_t)rhi * 128 + c0) = make_float2(acc[mt][nt][2], acc[mt][nt][3]);
            }
        }
        __syncthreads();
    }
}

// ---------------- Kernel 2: persistent tf32-MMA fused edge pipeline ----------------
// SMEM floats: W1t[128*68] W2t[128*132] A1[128*68] A2[128*132] b1s[128] b2s[128] i1s/i2s[128 int each]
#define EDGE_SMEM ((128*68 + 128*132 + 128*68 + 128*132 + 256 + 256) * 4)

__global__ __launch_bounds__(256) void edge_mma_kernel(const float* __restrict__ ef,
                                                       const int* __restrict__ idx1,
                                                       const int* __restrict__ idx2,
                                                       const float* __restrict__ b1,
                                                       const float* __restrict__ b2,
                                                       int E, int ntiles) {
    extern __shared__ float sm[];
    float* W1t = sm;
    float* W2t = W1t + 128 * 68;
    float* A1  = W2t + 128 * 132;
    float* A2  = A1 + 128 * 68;
    float* b1s = A2 + 128 * 132;
    float* b2s = b1s + 128;
    int* i1s = (int*)(b2s + 128);
    int* i2s = i1s + 128;

    int tid = threadIdx.x, wid = tid >> 5, lane = tid & 31;
    int g = lane >> 2, q = lane & 3;
    int mw = wid & 3, nw = wid >> 2;
    const float4* ef4 = (const float4*)ef;

    // persistent weights / biases
    for (int i = tid; i < 128 * 68 / 4; i += 256) ((float4*)W1t)[i] = ((const float4*)g_w1t)[i];
    for (int i = tid; i < 128 * 132 / 4; i += 256) ((float4*)W2t)[i] = ((const float4*)g_w2t)[i];
    if (tid < 128) { b1s[tid] = b1[tid]; b2s[tid] = b2[tid]; }

    // prologue: fill first tile directly
    int t = blockIdx.x;
    {
        int e0 = t * 128;
        #pragma unroll
        for (int c = 0; c < 8; c++) {
            int ci = c * 256 + tid;
            int m = ci >> 4, qq = ci & 15;
            int e = e0 + m;
            float4 v = {0.f, 0.f, 0.f, 0.f};
            if (e < E) v = ef4[(size_t)e * 16 + qq];
            float* dst = A1 + m * 68 + qq * 4;
            dst[0] = tf32r(v.x); dst[1] = tf32r(v.y); dst[2] = tf32r(v.z); dst[3] = tf32r(v.w);
        }
        int e = e0 + (tid & 127);
        int v = 0;
        if (e < E) v = (tid < 128) ? idx1[e] : idx2[e];
        if (tid < 128) i1s[tid] = v; else i2s[tid - 128] = v;
    }
    __syncthreads();

    for (; t < ntiles; t += gridDim.x) {
        int e0 = t * 128;
        int tn = t + gridDim.x;
        bool have_next = tn < ntiles;

        // register-prefetch next tile (LDG latency hidden under both GEMMs)
        float4 pf[8];
        int pidx = 0;
        if (have_next) {
            int ee0 = tn * 128;
            #pragma unroll
            for (int c = 0; c < 8; c++) {
                int ci = c * 256 + tid;
                int m = ci >> 4, qq = ci & 15;
                int e = ee0 + m;
                float4 v = {0.f, 0.f, 0.f, 0.f};
                if (e < E) v = ef4[(size_t)e * 16 + qq];
                pf[c] = v;
            }
            int e = ee0 + (tid & 127);
            if (e < E) pidx = (tid < 128) ? idx1[e] : idx2[e];
        }

        // ---- GEMM1: h = A1 @ W1^T (K=64) ----
        float acc[2][8][4];
        zero_acc(acc);
        mma_gemm<64, 68, 68>(A1, W1t, mw, nw, g, q, acc);

        // ---- epilogue 1: A2 = tf32(sp(h + b1)) ----
        #pragma unroll
        for (int mt = 0; mt < 2; mt++) {
            int r = mw * 32 + mt * 16 + g;
            #pragma unroll
            for (int nt = 0; nt < 8; nt++) {
                int c0 = nw * 64 + nt * 8 + 2 * q;
                float2 bb = *(const float2*)(b1s + c0);
                float2 v0, v1;
                v0.x = tf32r(sp_fast(acc[mt][nt][0] + bb.x));
                v0.y = tf32r(sp_fast(acc[mt][nt][1] + bb.y));
                v1.x = tf32r(sp_fast(acc[mt][nt][2] + bb.x));
                v1.y = tf32r(sp_fast(acc[mt][nt][3] + bb.y));
                *(float2*)(A2 + r * 132 + c0) = v0;
                *(float2*)(A2 + (r + 8) * 132 + c0) = v1;
            }
        }
        __syncthreads();

        // ---- GEMM2: W = A2 @ W2^T (K=128) ----
        zero_acc(acc);
        mma_gemm<128, 132, 132>(A2, W2t, mw, nw, g, q, acc);

        // ---- epilogue 2: w=sp(acc+b2); v4-red scatter w * x[idx2] into sums[idx1] ----
        bool evn = (q & 1) == 0;
        #pragma unroll
        for (int mt = 0; mt < 2; mt++) {
            int rlo = mw * 32 + mt * 16 + g, rhi = rlo + 8;
            int elo = e0 + rlo, ehi = e0 + rhi;
            int n1lo = i1s[rlo], n2lo = i2s[rlo];
            int n1hi = i1s[rhi], n2hi = i2s[rhi];
            const float* xlo_p = g_x + (size_t)n2lo * 128;
            const float* xhi_p = g_x + (size_t)n2hi * 128;
            float* slo = g_sums + (size_t)n1lo * 128;
            float* shi = g_sums + (size_t)n1hi * 128;
            #pragma unroll
            for (int nt = 0; nt < 8; nt++) {
                int c0 = nw * 64 + nt * 8 + 2 * q;
                float2 bb = *(const float2*)(b2s + c0);
                float2 xl = *(const float2*)(xlo_p + c0);
                float2 xh = *(const float2*)(xhi_p + c0);
                float a0 = sp_fast(acc[mt][nt][0] + bb.x) * xl.x;
                float a1 = sp_fast(acc[mt][nt][1] + bb.y) * xl.y;
                float a2 = sp_fast(acc[mt][nt][2] + bb.x) * xh.x;
                float a3 = sp_fast(acc[mt][nt][3] + bb.y) * xh.y;
                // pair exchange: even lane gathers row-lo quad, odd lane row-hi quad
                float s0 = __shfl_xor_sync(0xffffffffu, evn ? a2 : a0, 1);
                float s1 = __shfl_xor_sync(0xffffffffu, evn ? a3 : a1, 1);
                int cb = nw * 64 + nt * 8 + 4 * (q >> 1);
                if (evn) {
                    if (elo < E)
                        asm volatile("red.global.add.v4.f32 [%0], {%1,%2,%3,%4};"
                                     :: "l"(slo + cb), "f"(a0), "f"(a1), "f"(s0), "f"(s1) : "memory");
                } else {
                    if (ehi < E)
                        asm volatile("red.global.add.v4.f32 [%0], {%1,%2,%3,%4};"
                                     :: "l"(shi + cb), "f"(s0), "f"(s1), "f"(a2), "f"(a3) : "memory");
                }
            }
            if (nw == 0 && q == 0) {
                if (elo < E) atomicAdd(&g_cnt[n1lo], 1.0f);
                if (ehi < E) atomicAdd(&g_cnt[n1hi], 1.0f);
            }
        }
        __syncthreads();

        // store prefetched next tile
        if (have_next) {
            #pragma unroll
            for (int c = 0; c < 8; c++) {
                int ci = c * 256 + tid;
                int m = ci >> 4, qq = ci & 15;
                float* dst = A1 + m * 68 + qq * 4;
                dst[0] = tf32r(pf[c].x); dst[1] = tf32r(pf[c].y);
                dst[2] = tf32r(pf[c].z); dst[3] = tf32r(pf[c].w);
            }
            if (tid < 128) i1s[tid] = pidx; else i2s[tid - 128] = pidx;
        }
        __syncthreads();
    }
}

// ---------------- Kernel 3: node epilogue (tf32 MMA, persistent) ----------------
// mean = sums/max(cnt,1); h = sp(mean@W2+b2); out = node_fea + h@W3 + b3
#define NODE_SMEM ((128 * 132 * 3 + 128 + 256) * 4)
__global__ __launch_bounds__(256) void node_mma_kernel(const float* __restrict__ node_fea,
                                                       const float* __restrict__ baw2,
                                                       const float* __restrict__ baw3,
                                                       float* __restrict__ out,
                                                       int N, int ntiles) {
    extern __shared__ float sm[];
    float* W2t = sm;
    float* W3t = W2t + 128 * 132;
    float* As  = W3t + 128 * 132;
    float* inv = As + 128 * 132;     // 128
    float* b2s = inv + 128;          // 128
    float* b3s = b2s + 128;          // 128

    int tid = threadIdx.x, wid = tid >> 5, lane = tid & 31;
    int g = lane >> 2, q = lane & 3;
    int mw = wid & 3, nw = wid >> 2;

    for (int i = tid; i < 128 * 132 / 4; i += 256) {
        ((float4*)W2t)[i] = ((const float4*)g_waw2t)[i];
        ((float4*)W3t)[i] = ((const float4*)g_waw3t)[i];
    }
    if (tid < 128) { b2s[tid] = baw2[tid]; b3s[tid] = baw3[tid]; }

    for (int t = blockIdx.x; t < ntiles; t += gridDim.x) {
        int r0 = t * 128;
        if (tid < 128) {
            int r = r0 + tid;
            inv[tid] = (r < N) ? 1.f / fmaxf(g_cnt[r], 1.f) : 0.f;
        }
        __syncthreads();
        for (int c = 0; c < 16; c++) {
            int ci = c * 256 + tid;
            int m = ci >> 5, qq = ci & 31;
            int r = r0 + m;
            float4 v = {0.f, 0.f, 0.f, 0.f};
            if (r < N) v = ((const float4*)g_sums)[(size_t)r * 32 + qq];
            float iv = inv[m];
            float* dst = As + m * 132 + qq * 4;
            dst[0] = tf32r(v.x * iv); dst[1] = tf32r(v.y * iv);
            dst[2] = tf32r(v.z * iv); dst[3] = tf32r(v.w * iv);
        }
        __syncthreads();

        float acc[2][8][4];
        zero_acc(acc);
        mma_gemm<128, 132, 132>(As, W2t, mw, nw, g, q, acc);

        // h = tf32(sp(acc + b2)) in regs
        #pragma unroll
        for (int mt = 0; mt < 2; mt++)
            #pragma unroll
            for (int nt = 0; nt < 8; nt++) {
                int c0 = nw * 64 + nt * 8 + 2 * q;
                float2 bb = *(const float2*)(b2s + c0);
                acc[mt][nt][0] = tf32r(sp_fast(acc[mt][nt][0] + bb.x));
                acc[mt][nt][1] = tf32r(sp_fast(acc[mt][nt][1] + bb.y));
                acc[mt][nt][2] = tf32r(sp_fast(acc[mt][nt][2] + bb.x));
                acc[mt][nt][3] = tf32r(sp_fast(acc[mt][nt][3] + bb.y));
            }
        __syncthreads();   // all GEMM1 reads of As done
        #pragma unroll
        for (int mt = 0; mt < 2; mt++) {
            int r = mw * 32 + mt * 16 + g;
            #pragma unroll
            for (int nt = 0; nt < 8; nt++) {
                int c0 = nw * 64 + nt * 8 + 2 * q;
                *(float2*)(As + r * 132 + c0) = make_float2(acc[mt][nt][0], acc[mt][nt][1]);
                *(float2*)(As + (r + 8) * 132 + c0) = make_float2(acc[mt][nt][2], acc[mt][nt][3]);
            }
        }
        __syncthreads();

        zero_acc(acc);
        mma_gemm<128, 132, 132>(As, W3t, mw, nw, g, q, acc);

        #pragma unroll
        for (int mt = 0; mt < 2; mt++) {
            int rlo = r0 + mw * 32 + mt * 16 + g, rhi = rlo + 8;
            #pragma unroll
            for (int nt = 0; nt < 8; nt++) {
                int c0 = nw * 64 + nt * 8 + 2 * q;
                float2 bb = *(const float2*)(b3s + c0);
                if (rlo < N) {
                    float2 nf = *(const float2*)(node_fea + (size_t)rlo * 128 + c0);
                    *(float2*)(out + (size_t)rlo * 128 + c0) =
                        make_float2(nf.x + acc[mt][nt][0] + bb.x, nf.y + acc[mt][nt][1] + bb.y);
                }
                if (rhi < N) {
                    float2 nf = *(const float2*)(node_fea + (size_t)rhi * 128 + c0);
                    *(float2*)(out + (size_t)rhi * 128 + c0) =
                        make_float2(nf.x + acc[mt][nt][2] + bb.x, nf.y + acc[mt][nt][3] + bb.y);
                }
            }
        }
        __syncthreads();
    }
}

extern "C" void kernel_launch(void* const* d_in, const int* in_sizes, int n_in,
                              void* d_out, int out_size) {
    const float* node_fea = (const float*)d_in[0];
    const int*   idx1     = (const int*)d_in[1];
    const int*   idx2     = (const int*)d_in[2];
    const float* edge_fea = (const float*)d_in[3];
    const float* W_aw1    = (const float*)d_in[4];
    const float* W_fg1    = (const float*)d_in[5];
    const float* b_fg1    = (const float*)d_in[6];
    const float* W_fg2    = (const float*)d_in[7];
    const float* b_fg2    = (const float*)d_in[8];
    const float* W_aw2    = (const float*)d_in[9];
    const float* b_aw2    = (const float*)d_in[10];
    const float* W_aw3    = (const float*)d_in[11];
    const float* b_aw3    = (const float*)d_in[12];

    int N = in_sizes[0] / 128;
    int E = in_sizes[1];
    float* out = (float*)d_out;

    void *p_sums, *p_cnt;
    cudaGetSymbolAddress(&p_sums, g_sums);
    cudaGetSymbolAddress(&p_cnt, g_cnt);
    cudaMemsetAsync(p_sums, 0, (size_t)N * 128 * sizeof(float));
    cudaMemsetAsync(p_cnt, 0, (size_t)N * sizeof(float));

    cudaFuncSetAttribute(gemm_x_mma, cudaFuncAttributeMaxDynamicSharedMemorySize, XK_SMEM);
    cudaFuncSetAttribute(edge_mma_kernel, cudaFuncAttributeMaxDynamicSharedMemorySize, EDGE_SMEM);
    cudaFuncSetAttribute(node_mma_kernel, cudaFuncAttributeMaxDynamicSharedMemorySize, NODE_SMEM);

    int ntN = (N + 127) / 128;
    int ntE = (E + 127) / 128;
    int gbN = ntN < 148 ? ntN : 148;
    int gbE = ntE < 148 ? ntE : 148;

    prep_weights<<<32, 256>>>(W_fg1, W_fg2, W_aw1, W_aw2, W_aw3);
    gemm_x_mma<<<gbN, 256, XK_SMEM>>>(node_fea, N, ntN);
    edge_mma_kernel<<<gbE, 256, EDGE_SMEM>>>(edge_fea, idx1, idx2, b_fg1, b_fg2, E, ntE);
    node_mma_kernel<<<gbN, 256, NODE_SMEM>>>(node_fea, b_aw2, b_aw3, out, N, ntN);
}

// round 5
// speedup vs baseline: 4.9812x; 1.7480x over previous
#include <cuda_runtime.h>
#include <cuda_bf16.h>
#include <math.h>
#include <stdint.h>

typedef unsigned long long u64;

#define NMAX 50000
#define EMAX 640000

// Scratch (static __device__ arrays per allocation rules)
__device__ float g_x[(size_t)NMAX * 128];
__device__ float g_sums[(size_t)NMAX * 128];
__device__ float g_cnt[NMAX];
// bf16 weight images, [n][k] transposed, padded strides (72 for K=64, 136 for K=128)
__device__ __align__(16) __nv_bfloat16 g_w1b[128 * 72];
__device__ __align__(16) __nv_bfloat16 g_w2b[128 * 136];
__device__ __align__(16) __nv_bfloat16 g_wa1b[128 * 136];
__device__ __align__(16) __nv_bfloat16 g_wa2b[128 * 136];
__device__ __align__(16) __nv_bfloat16 g_wa3b[128 * 136];

// fast softplus - ln2 via MUFU
__device__ __forceinline__ float sp_fast(float x) {
    float t = __expf(-fabsf(x));
    return fmaxf(x, 0.f) + __logf(1.f + t) - 0.69314718055994531f;
}

__device__ __forceinline__ uint32_t smem_u32(const void* p) {
    uint32_t a;
    asm("{ .reg .u64 t; cvta.to.shared.u64 t, %1; cvt.u32.u64 %0, t; }" : "=r"(a) : "l"(p));
    return a;
}
__device__ __forceinline__ void ldsm4(uint32_t& r0, uint32_t& r1, uint32_t& r2, uint32_t& r3, uint32_t addr) {
    asm volatile("ldmatrix.sync.aligned.m8n8.x4.shared.b16 {%0,%1,%2,%3}, [%4];"
                 : "=r"(r0), "=r"(r1), "=r"(r2), "=r"(r3) : "r"(addr));
}
__device__ __forceinline__ void mma16(float d[4], const uint32_t a[4], uint32_t b0, uint32_t b1) {
    asm("mma.sync.aligned.m16n8k16.row.col.f32.bf16.bf16.f32 "
        "{%0,%1,%2,%3}, {%4,%5,%6,%7}, {%8,%9}, {%0,%1,%2,%3};"
        : "+f"(d[0]), "+f"(d[1]), "+f"(d[2]), "+f"(d[3])
        : "r"(a[0]), "r"(a[1]), "r"(a[2]), "r"(a[3]), "r"(b0), "r"(b1));
}
__device__ __forceinline__ void zero_acc(float acc[2][8][4]) {
    #pragma unroll
    for (int a = 0; a < 2; a++)
        #pragma unroll
        for (int b = 0; b < 8; b++)
            #pragma unroll
            for (int c = 0; c < 4; c++) acc[a][b][c] = 0.f;
}
__device__ __forceinline__ uint32_t pack_bf(float lo, float hi) {
    __nv_bfloat162 p = __floats2bfloat162_rn(lo, hi);
    return *(uint32_t*)&p;
}

// Warp GEMM via ldmatrix + bf16 mma. S = row stride in bf16 elems.
// Abase/Bbase: smem u32 addr already including lane row/khalf offsets.
template<int K, int S>
__device__ __forceinline__ void wgemm(uint32_t Abase, uint32_t Bbase, float acc[2][8][4]) {
    #pragma unroll
    for (int kk = 0; kk < K; kk += 16) {
        uint32_t a[2][4];
        #pragma unroll
        for (int mt = 0; mt < 2; mt++)
            ldsm4(a[mt][0], a[mt][1], a[mt][2], a[mt][3], Abase + (mt * 16 * S + kk) * 2);
        #pragma unroll
        for (int p = 0; p < 4; p++) {
            uint32_t b0, b1, b2, b3;
            ldsm4(b0, b1, b2, b3, Bbase + (p * 16 * S + kk) * 2);
            mma16(acc[0][2 * p], a[0], b0, b1);
            mma16(acc[1][2 * p], a[1], b0, b1);
            mma16(acc[0][2 * p + 1], a[0], b2, b3);
            mma16(acc[1][2 * p + 1], a[1], b2, b3);
        }
    }
}

// ------------- prep: transpose + bf16-round all weights -------------
__global__ void prep_weights(const float* __restrict__ W1, const float* __restrict__ W2,
                             const float* __restrict__ Wa1, const float* __restrict__ Wa2,
                             const float* __restrict__ Wa3) {
    int t = blockIdx.x * blockDim.x + threadIdx.x;
    int stride = blockDim.x * gridDim.x;
    for (int i = t; i < 64 * 128; i += stride) {
        int k = i >> 7, n = i & 127;
        g_w1b[n * 72 + k] = __float2bfloat16(W1[i]);
    }
    for (int i = t; i < 128 * 128; i += stride) {
        int k = i >> 7, n = i & 127;
        g_w2b[n * 136 + k] = __float2bfloat16(W2[i]);
        g_wa1b[n * 136 + k] = __float2bfloat16(Wa1[i]);
        g_wa2b[n * 136 + k] = __float2bfloat16(Wa2[i]);
        g_wa3b[n * 136 + k] = __float2bfloat16(Wa3[i]);
    }
}

// ---------------- Kernel 1: x = node_fea @ W_aw1 (bf16 MMA, persistent) ----------------
#define XK_SMEM ((128 * 136 * 2) * 2)
__global__ __launch_bounds__(256, 2) void gemm_x_mma(const float* __restrict__ A,
                                                     int N, int ntiles) {
    extern __shared__ char smc[];
    __nv_bfloat16* Wt = (__nv_bfloat16*)smc;
    __nv_bfloat16* As = Wt + 128 * 136;
    int tid = threadIdx.x, wid = tid >> 5, lane = tid & 31;
    int g = lane >> 2, q = lane & 3;
    int mw = wid & 3, nw = wid >> 2;
    int arow = (lane & 7) + ((lane >> 3) & 1) * 8, ak = lane >> 4;
    int brow = (lane & 7) + ((lane >> 4) << 3), bk = (lane >> 3) & 1;

    for (int i = tid; i < 128 * 136 * 2 / 16; i += 256) ((uint4*)Wt)[i] = ((const uint4*)g_wa1b)[i];
    uint32_t As_u = smem_u32(As), Wt_u = smem_u32(Wt);
    uint32_t Ab = As_u + ((mw * 32 + arow) * 136 + ak * 8) * 2;
    uint32_t Bb = Wt_u + ((nw * 64 + brow) * 136 + bk * 8) * 2;

    for (int t = blockIdx.x; t < ntiles; t += gridDim.x) {
        int r0 = t * 128;
        #pragma unroll
        for (int c = 0; c < 16; c++) {
            int ci = c * 256 + tid;
            int m = ci >> 5, qq = ci & 31;
            int r = r0 + m;
            float4 v = {0.f, 0.f, 0.f, 0.f};
            if (r < N) v = ((const float4*)A)[(size_t)r * 32 + qq];
            uint2 pv = {pack_bf(v.x, v.y), pack_bf(v.z, v.w)};
            *(uint2*)((char*)As + (m * 136 + qq * 4) * 2) = pv;
        }
        __syncthreads();
        float acc[2][8][4];
        zero_acc(acc);
        wgemm<128, 136>(Ab, Bb, acc);
        #pragma unroll
        for (int mt = 0; mt < 2; mt++) {
            int rlo = r0 + mw * 32 + mt * 16 + g, rhi = rlo + 8;
            #pragma unroll
            for (int nt = 0; nt < 8; nt++) {
                int c0 = nw * 64 + nt * 8 + 2 * q;
                if (rlo < N) *(float2*)(g_x + (size_t)rlo * 128 + c0) = make_float2(acc[mt][nt][0], acc[mt][nt][1]);
                if (rhi < N) *(float2*)(g_x + (size_t)rhi * 128 + c0) = make_float2(acc[mt][nt][2], acc[mt][nt][3]);
            }
        }
        __syncthreads();
    }
}

// ---------------- Kernel 2: persistent bf16-MMA fused edge pipeline ----------------
// bf16: W1t[128*72] W2t[128*136] A1[128*72] A2[128*136]; f32: b1s,b2s[128]; int: i1s,i2s[128]
#define EDGE_SMEM ((128 * 72 + 128 * 136 + 128 * 72 + 128 * 136) * 2 + 512 * 2 + 512 * 2)

__global__ __launch_bounds__(256, 2) void edge_mma_kernel(const float* __restrict__ ef,
                                                          const int* __restrict__ idx1,
                                                          const int* __restrict__ idx2,
                                                          const float* __restrict__ b1,
                                                          const float* __restrict__ b2,
                                                          int E, int ntiles) {
    extern __shared__ char smc[];
    __nv_bfloat16* W1t = (__nv_bfloat16*)smc;
    __nv_bfloat16* W2t = W1t + 128 * 72;
    __nv_bfloat16* A1  = W2t + 128 * 136;
    __nv_bfloat16* A2  = A1 + 128 * 72;
    float* b1s = (float*)(A2 + 128 * 136);
    float* b2s = b1s + 128;
    int* i1s = (int*)(b2s + 128);
    int* i2s = i1s + 128;

    int tid = threadIdx.x, wid = tid >> 5, lane = tid & 31;
    int g = lane >> 2, q = lane & 3;
    int mw = wid & 3, nw = wid >> 2;
    int arow = (lane & 7) + ((lane >> 3) & 1) * 8, ak = lane >> 4;
    int brow = (lane & 7) + ((lane >> 4) << 3), bk = (lane >> 3) & 1;
    const float4* ef4 = (const float4*)ef;

    // persistent weights / biases
    for (int i = tid; i < 128 * 72 * 2 / 16; i += 256) ((uint4*)W1t)[i] = ((const uint4*)g_w1b)[i];
    for (int i = tid; i < 128 * 136 * 2 / 16; i += 256) ((uint4*)W2t)[i] = ((const uint4*)g_w2b)[i];
    if (tid < 128) { b1s[tid] = b1[tid]; b2s[tid] = b2[tid]; }

    uint32_t A1u = smem_u32(A1), A2u = smem_u32(A2);
    uint32_t W1u = smem_u32(W1t), W2u = smem_u32(W2t);
    uint32_t A1b = A1u + ((mw * 32 + arow) * 72 + ak * 8) * 2;
    uint32_t B1b = W1u + ((nw * 64 + brow) * 72 + bk * 8) * 2;
    uint32_t A2b = A2u + ((mw * 32 + arow) * 136 + ak * 8) * 2;
    uint32_t B2b = W2u + ((nw * 64 + brow) * 136 + bk * 8) * 2;

    int t = blockIdx.x;
    if (t < ntiles) {
        int e0 = t * 128;
        #pragma unroll
        for (int c = 0; c < 8; c++) {
            int ci = c * 256 + tid;
            int m = ci >> 4, qq = ci & 15;
            int e = e0 + m;
            float4 v = {0.f, 0.f, 0.f, 0.f};
            if (e < E) v = ef4[(size_t)e * 16 + qq];
            uint2 pv = {pack_bf(v.x, v.y), pack_bf(v.z, v.w)};
            *(uint2*)((char*)A1 + (m * 72 + qq * 4) * 2) = pv;
        }
        int e = e0 + (tid & 127);
        int v = 0;
        if (e < E) v = (tid < 128) ? idx1[e] : idx2[e];
        if (tid < 128) i1s[tid] = v; else i2s[tid - 128] = v;
    }
    __syncthreads();

    for (; t < ntiles; t += gridDim.x) {
        int e0 = t * 128;
        int tn = t + gridDim.x;
        bool have_next = tn < ntiles;

        // register-prefetch next tile
        float4 pf[8];
        int pidx = 0;
        if (have_next) {
            int ee0 = tn * 128;
            #pragma unroll
            for (int c = 0; c < 8; c++) {
                int ci = c * 256 + tid;
                int m = ci >> 4, qq = ci & 15;
                int e = ee0 + m;
                float4 v = {0.f, 0.f, 0.f, 0.f};
                if (e < E) v = ef4[(size_t)e * 16 + qq];
                pf[c] = v;
            }
            int e = ee0 + (tid & 127);
            if (e < E) pidx = (tid < 128) ? idx1[e] : idx2[e];
        }

        // ---- GEMM1: h = A1 @ W1^T (K=64) ----
        float acc[2][8][4];
        zero_acc(acc);
        wgemm<64, 72>(A1b, B1b, acc);

        // ---- epilogue 1: A2 = bf16(sp(h + b1)) ----
        #pragma unroll
        for (int mt = 0; mt < 2; mt++) {
            int r = mw * 32 + mt * 16 + g;
            #pragma unroll
            for (int nt = 0; nt < 8; nt++) {
                int c0 = nw * 64 + nt * 8 + 2 * q;
                float2 bb = *(const float2*)(b1s + c0);
                uint32_t lo = pack_bf(sp_fast(acc[mt][nt][0] + bb.x), sp_fast(acc[mt][nt][1] + bb.y));
                uint32_t hi = pack_bf(sp_fast(acc[mt][nt][2] + bb.x), sp_fast(acc[mt][nt][3] + bb.y));
                *(uint32_t*)((char*)A2 + (r * 136 + c0) * 2) = lo;
                *(uint32_t*)((char*)A2 + ((r + 8) * 136 + c0) * 2) = hi;
            }
        }
        __syncthreads();

        // ---- GEMM2: W = A2 @ W2^T (K=128) ----
        zero_acc(acc);
        wgemm<128, 136>(A2b, B2b, acc);

        // ---- epilogue 2: w=sp(acc+b2); v4-red scatter w * x[idx2] into sums[idx1] ----
        bool evn = (q & 1) == 0;
        #pragma unroll
        for (int mt = 0; mt < 2; mt++) {
            int rlo = mw * 32 + mt * 16 + g, rhi = rlo + 8;
            int elo = e0 + rlo, ehi = e0 + rhi;
            int n1lo = i1s[rlo], n2lo = i2s[rlo];
            int n1hi = i1s[rhi], n2hi = i2s[rhi];
            const float* xlo_p = g_x + (size_t)n2lo * 128;
            const float* xhi_p = g_x + (size_t)n2hi * 128;
            float* slo = g_sums + (size_t)n1lo * 128;
            float* shi = g_sums + (size_t)n1hi * 128;
            #pragma unroll
            for (int nt = 0; nt < 8; nt++) {
                int c0 = nw * 64 + nt * 8 + 2 * q;
                float2 bb = *(const float2*)(b2s + c0);
                float2 xl = *(const float2*)(xlo_p + c0);
                float2 xh = *(const float2*)(xhi_p + c0);
                float a0 = sp_fast(acc[mt][nt][0] + bb.x) * xl.x;
                float a1 = sp_fast(acc[mt][nt][1] + bb.y) * xl.y;
                float a2 = sp_fast(acc[mt][nt][2] + bb.x) * xh.x;
                float a3 = sp_fast(acc[mt][nt][3] + bb.y) * xh.y;
                float s0 = __shfl_xor_sync(0xffffffffu, evn ? a2 : a0, 1);
                float s1 = __shfl_xor_sync(0xffffffffu, evn ? a3 : a1, 1);
                int cb = nw * 64 + nt * 8 + 4 * (q >> 1);
                if (evn) {
                    if (elo < E)
                        asm volatile("red.global.add.v4.f32 [%0], {%1,%2,%3,%4};"
                                     :: "l"(slo + cb), "f"(a0), "f"(a1), "f"(s0), "f"(s1) : "memory");
                } else {
                    if (ehi < E)
                        asm volatile("red.global.add.v4.f32 [%0], {%1,%2,%3,%4};"
                                     :: "l"(shi + cb), "f"(s0), "f"(s1), "f"(a2), "f"(a3) : "memory");
                }
            }
            if (nw == 0 && q == 0) {
                if (elo < E) atomicAdd(&g_cnt[n1lo], 1.0f);
                if (ehi < E) atomicAdd(&g_cnt[n1hi], 1.0f);
            }
        }
        __syncthreads();

        if (have_next) {
            #pragma unroll
            for (int c = 0; c < 8; c++) {
                int ci = c * 256 + tid;
                int m = ci >> 4, qq = ci & 15;
                uint2 pv = {pack_bf(pf[c].x, pf[c].y), pack_bf(pf[c].z, pf[c].w)};
                *(uint2*)((char*)A1 + (m * 72 + qq * 4) * 2) = pv;
            }
            if (tid < 128) i1s[tid] = pidx; else i2s[tid - 128] = pidx;
        }
        __syncthreads();
    }
}

// ---------------- Kernel 3: node epilogue (bf16 MMA, persistent) ----------------
#define NODE_SMEM ((128 * 136 * 3) * 2 + 128 * 4 * 3)
__global__ __launch_bounds__(256, 2) void node_mma_kernel(const float* __restrict__ node_fea,
                                                          const float* __restrict__ baw2,
                                                          const float* __restrict__ baw3,
                                                          float* __restrict__ out,
                                                          int N, int ntiles) {
    extern __shared__ char smc[];
    __nv_bfloat16* W2t = (__nv_bfloat16*)smc;
    __nv_bfloat16* W3t = W2t + 128 * 136;
    __nv_bfloat16* As  = W3t + 128 * 136;
    float* inv = (float*)(As + 128 * 136);
    float* b2s = inv + 128;
    float* b3s = b2s + 128;

    int tid = threadIdx.x, wid = tid >> 5, lane = tid & 31;
    int g = lane >> 2, q = lane & 3;
    int mw = wid & 3, nw = wid >> 2;
    int arow = (lane & 7) + ((lane >> 3) & 1) * 8, ak = lane >> 4;
    int brow = (lane & 7) + ((lane >> 4) << 3), bk = (lane >> 3) & 1;

    for (int i = tid; i < 128 * 136 * 2 / 16; i += 256) {
        ((uint4*)W2t)[i] = ((const uint4*)g_wa2b)[i];
        ((uint4*)W3t)[i] = ((const uint4*)g_wa3b)[i];
    }
    if (tid < 128) { b2s[tid] = baw2[tid]; b3s[tid] = baw3[tid]; }

    uint32_t As_u = smem_u32(As);
    uint32_t Ab = As_u + ((mw * 32 + arow) * 136 + ak * 8) * 2;
    uint32_t B2b = smem_u32(W2t) + ((nw * 64 + brow) * 136 + bk * 8) * 2;
    uint32_t B3b = smem_u32(W3t) + ((nw * 64 + brow) * 136 + bk * 8) * 2;

    for (int t = blockIdx.x; t < ntiles; t += gridDim.x) {
        int r0 = t * 128;
        if (tid < 128) {
            int r = r0 + tid;
            inv[tid] = (r < N) ? 1.f / fmaxf(g_cnt[r], 1.f) : 0.f;
        }
        __syncthreads();
        #pragma unroll
        for (int c = 0; c < 16; c++) {
            int ci = c * 256 + tid;
            int m = ci >> 5, qq = ci & 31;
            int r = r0 + m;
            float4 v = {0.f, 0.f, 0.f, 0.f};
            if (r < N) v = ((const float4*)g_sums)[(size_t)r * 32 + qq];
            float iv = inv[m];
            uint2 pv = {pack_bf(v.x * iv, v.y * iv), pack_bf(v.z * iv, v.w * iv)};
            *(uint2*)((char*)As + (m * 136 + qq * 4) * 2) = pv;
        }
        __syncthreads();

        float acc[2][8][4];
        zero_acc(acc);
        wgemm<128, 136>(Ab, B2b, acc);

        // h = bf16(sp(acc + b2))
        uint32_t hlo[2][8], hhi[2][8];
        #pragma unroll
        for (int mt = 0; mt < 2; mt++)
            #pragma unroll
            for (int nt = 0; nt < 8; nt++) {
                int c0 = nw * 64 + nt * 8 + 2 * q;
                float2 bb = *(const float2*)(b2s + c0);
                hlo[mt][nt] = pack_bf(sp_fast(acc[mt][nt][0] + bb.x), sp_fast(acc[mt][nt][1] + bb.y));
                hhi[mt][nt] = pack_bf(sp_fast(acc[mt][nt][2] + bb.x), sp_fast(acc[mt][nt][3] + bb.y));
            }
        __syncthreads();
        #pragma unroll
        for (int mt = 0; mt < 2; mt++) {
            int r = mw * 32 + mt * 16 + g;
            #pragma unroll
            for (int nt = 0; nt < 8; nt++) {
                int c0 = nw * 64 + nt * 8 + 2 * q;
                *(uint32_t*)((char*)As + (r * 136 + c0) * 2) = hlo[mt][nt];
                *(uint32_t*)((char*)As + ((r + 8) * 136 + c0) * 2) = hhi[mt][nt];
            }
        }
        __syncthreads();

        zero_acc(acc);
        wgemm<128, 136>(Ab, B3b, acc);

        #pragma unroll
        for (int mt = 0; mt < 2; mt++) {
            int rlo = r0 + mw * 32 + mt * 16 + g, rhi = rlo + 8;
            #pragma unroll
            for (int nt = 0; nt < 8; nt++) {
                int c0 = nw * 64 + nt * 8 + 2 * q;
                float2 bb = *(const float2*)(b3s + c0);
                if (rlo < N) {
                    float2 nf = *(const float2*)(node_fea + (size_t)rlo * 128 + c0);
                    *(float2*)(out + (size_t)rlo * 128 + c0) =
                        make_float2(nf.x + acc[mt][nt][0] + bb.x, nf.y + acc[mt][nt][1] + bb.y);
                }
                if (rhi < N) {
                    float2 nf = *(const float2*)(node_fea + (size_t)rhi * 128 + c0);
                    *(float2*)(out + (size_t)rhi * 128 + c0) =
                        make_float2(nf.x + acc[mt][nt][2] + bb.x, nf.y + acc[mt][nt][3] + bb.y);
                }
            }
        }
        __syncthreads();
    }
}

extern "C" void kernel_launch(void* const* d_in, const int* in_sizes, int n_in,
                              void* d_out, int out_size) {
    const float* node_fea = (const float*)d_in[0];
    const int*   idx1     = (const int*)d_in[1];
    const int*   idx2     = (const int*)d_in[2];
    const float* edge_fea = (const float*)d_in[3];
    const float* W_aw1    = (const float*)d_in[4];
    const float* W_fg1    = (const float*)d_in[5];
    const float* b_fg1    = (const float*)d_in[6];
    const float* W_fg2    = (const float*)d_in[7];
    const float* b_fg2    = (const float*)d_in[8];
    const float* W_aw2    = (const float*)d_in[9];
    const float* b_aw2    = (const float*)d_in[10];
    const float* W_aw3    = (const float*)d_in[11];
    const float* b_aw3    = (const float*)d_in[12];

    int N = in_sizes[0] / 128;
    int E = in_sizes[1];
    float* out = (float*)d_out;

    void *p_sums, *p_cnt;
    cudaGetSymbolAddress(&p_sums, g_sums);
    cudaGetSymbolAddress(&p_cnt, g_cnt);
    cudaMemsetAsync(p_sums, 0, (size_t)N * 128 * sizeof(float));
    cudaMemsetAsync(p_cnt, 0, (size_t)N * sizeof(float));

    cudaFuncSetAttribute(gemm_x_mma, cudaFuncAttributeMaxDynamicSharedMemorySize, XK_SMEM);
    cudaFuncSetAttribute(edge_mma_kernel, cudaFuncAttributeMaxDynamicSharedMemorySize, EDGE_SMEM);
    cudaFuncSetAttribute(node_mma_kernel, cudaFuncAttributeMaxDynamicSharedMemorySize, NODE_SMEM);

    int ntN = (N + 127) / 128;
    int ntE = (E + 127) / 128;
    int gbN = ntN < 296 ? ntN : 296;
    int gbE = ntE < 296 ? ntE : 296;

    prep_weights<<<64, 256>>>(W_fg1, W_fg2, W_aw1, W_aw2, W_aw3);
    gemm_x_mma<<<gbN, 256, XK_SMEM>>>(node_fea, N, ntN);
    edge_mma_kernel<<<gbE, 256, EDGE_SMEM>>>(edge_fea, idx1, idx2, b_fg1, b_fg2, E, ntE);
    node_mma_kernel<<<gbN, 256, NODE_SMEM>>>(node_fea, b_aw2, b_aw3, out, N, ntN);
}

// round 6
// speedup vs baseline: 5.0147x; 1.0067x over previous
#include <cuda_runtime.h>
#include <cuda_bf16.h>
#include <math.h>
#include <stdint.h>

typedef unsigned long long u64;

#define NMAX 50000
#define EMAX 640000

// Scratch (static __device__ arrays per allocation rules)
__device__ float g_x[(size_t)NMAX * 128];
__device__ float g_sums[(size_t)NMAX * 128];
__device__ float g_cnt[NMAX];
// Edge-kernel weight images: XOR-swizzled, unpadded K-major [n][k] bf16
__device__ __align__(16) char g_w1s[128 * 128];   // W_fg1^T, K=64, 128B/row
__device__ __align__(16) char g_w2s[128 * 256];   // W_fg2^T, K=128, 256B/row
// Node/x kernels: padded (136) non-swizzled bf16 images
__device__ __align__(16) __nv_bfloat16 g_wa1b[128 * 136];
__device__ __align__(16) __nv_bfloat16 g_wa2b[128 * 136];
__device__ __align__(16) __nv_bfloat16 g_wa3b[128 * 136];

// fast softplus - ln2 via MUFU
__device__ __forceinline__ float sp_fast(float x) {
    float t = __expf(-fabsf(x));
    return fmaxf(x, 0.f) + __logf(1.f + t) - 0.69314718055994531f;
}
__device__ __forceinline__ uint32_t smem_u32(const void* p) {
    uint32_t a;
    asm("{ .reg .u64 t; cvta.to.shared.u64 t, %1; cvt.u32.u64 %0, t; }" : "=r"(a) : "l"(p));
    return a;
}
__device__ __forceinline__ void ldsm4(uint32_t& r0, uint32_t& r1, uint32_t& r2, uint32_t& r3, uint32_t addr) {
    asm volatile("ldmatrix.sync.aligned.m8n8.x4.shared.b16 {%0,%1,%2,%3}, [%4];"
                 : "=r"(r0), "=r"(r1), "=r"(r2), "=r"(r3) : "r"(addr));
}
__device__ __forceinline__ void mma16(float d[4], const uint32_t a[4], uint32_t b0, uint32_t b1) {
    asm("mma.sync.aligned.m16n8k16.row.col.f32.bf16.bf16.f32 "
        "{%0,%1,%2,%3}, {%4,%5,%6,%7}, {%8,%9}, {%0,%1,%2,%3};"
        : "+f"(d[0]), "+f"(d[1]), "+f"(d[2]), "+f"(d[3])
        : "r"(a[0]), "r"(a[1]), "r"(a[2]), "r"(a[3]), "r"(b0), "r"(b1));
}
__device__ __forceinline__ uint32_t pack_bf(float lo, float hi) {
    __nv_bfloat162 p = __floats2bfloat162_rn(lo, hi);
    return *(uint32_t*)&p;
}
// swizzled byte offset: 16B chunk index XORed with (row & 7)
__device__ __forceinline__ uint32_t swz(int row, int chunk, int RB) {
    return (uint32_t)(row * RB + (((chunk ^ (row & 7)) & (RB / 16 - 1)) << 4));
}

// ---- swizzled warp GEMM, 32(m) x 32(n) warp tile ----
// arow: absolute A row for this lane (mt=0); brow0: absolute B row (p=0); ak/bk: k-half.
template<int K, int RB>
__device__ __forceinline__ void wgemm_sw(uint32_t Au, int arow, int ak,
                                         uint32_t Bu, int brow0, int bk,
                                         float acc[2][4][4]) {
    #pragma unroll
    for (int kk = 0; kk < K; kk += 16) {
        int kc = kk >> 3;
        uint32_t a[2][4];
        #pragma unroll
        for (int mt = 0; mt < 2; mt++)
            ldsm4(a[mt][0], a[mt][1], a[mt][2], a[mt][3], Au + swz(arow + mt * 16, kc + ak, RB));
        #pragma unroll
        for (int p = 0; p < 2; p++) {
            uint32_t b0, b1, b2, b3;
            ldsm4(b0, b1, b2, b3, Bu + swz(brow0 + p * 16, kc + bk, RB));
            mma16(acc[0][2 * p], a[0], b0, b1);
            mma16(acc[1][2 * p], a[1], b0, b1);
            mma16(acc[0][2 * p + 1], a[0], b2, b3);
            mma16(acc[1][2 * p + 1], a[1], b2, b3);
        }
    }
}

// ---- padded non-swizzled warp GEMM (node / x kernels), 32x64 tile ----
__device__ __forceinline__ void zero8(float acc[2][8][4]) {
    #pragma unroll
    for (int a = 0; a < 2; a++)
        #pragma unroll
        for (int b = 0; b < 8; b++)
            #pragma unroll
            for (int c = 0; c < 4; c++) acc[a][b][c] = 0.f;
}
template<int K, int S>
__device__ __forceinline__ void wgemm(uint32_t Abase, uint32_t Bbase, float acc[2][8][4]) {
    #pragma unroll
    for (int kk = 0; kk < K; kk += 16) {
        uint32_t a[2][4];
        #pragma unroll
        for (int mt = 0; mt < 2; mt++)
            ldsm4(a[mt][0], a[mt][1], a[mt][2], a[mt][3], Abase + (mt * 16 * S + kk) * 2);
        #pragma unroll
        for (int p = 0; p < 4; p++) {
            uint32_t b0, b1, b2, b3;
            ldsm4(b0, b1, b2, b3, Bbase + (p * 16 * S + kk) * 2);
            mma16(acc[0][2 * p], a[0], b0, b1);
            mma16(acc[1][2 * p], a[1], b0, b1);
            mma16(acc[0][2 * p + 1], a[0], b2, b3);
            mma16(acc[1][2 * p + 1], a[1], b2, b3);
        }
    }
}

// ------------- prep: transpose + bf16 all weights -------------
__global__ void prep_weights(const float* __restrict__ W1, const float* __restrict__ W2,
                             const float* __restrict__ Wa1, const float* __restrict__ Wa2,
                             const float* __restrict__ Wa3) {
    int t = blockIdx.x * blockDim.x + threadIdx.x;
    int stride = blockDim.x * gridDim.x;
    for (int i = t; i < 64 * 128; i += stride) {
        int k = i >> 7, n = i & 127;
        *(__nv_bfloat16*)(g_w1s + swz(n, k >> 3, 128) + (k & 7) * 2) = __float2bfloat16(W1[i]);
    }
    for (int i = t; i < 128 * 128; i += stride) {
        int k = i >> 7, n = i & 127;
        *(__nv_bfloat16*)(g_w2s + swz(n, k >> 3, 256) + (k & 7) * 2) = __float2bfloat16(W2[i]);
        g_wa1b[n * 136 + k] = __float2bfloat16(Wa1[i]);
        g_wa2b[n * 136 + k] = __float2bfloat16(Wa2[i]);
        g_wa3b[n * 136 + k] = __float2bfloat16(Wa3[i]);
    }
}

// ---------------- Kernel 1: x = node_fea @ W_aw1 (bf16 MMA, persistent) ----------------
#define XK_SMEM ((128 * 136 * 2) * 2)
__global__ __launch_bounds__(256, 2) void gemm_x_mma(const float* __restrict__ A,
                                                     int N, int ntiles) {
    extern __shared__ char smc[];
    __nv_bfloat16* Wt = (__nv_bfloat16*)smc;
    __nv_bfloat16* As = Wt + 128 * 136;
    int tid = threadIdx.x, wid = tid >> 5, lane = tid & 31;
    int g = lane >> 2, q = lane & 3;
    int mw = wid & 3, nw = wid >> 2;
    int arow = (lane & 7) + ((lane >> 3) & 1) * 8, ak = lane >> 4;
    int brow = (lane & 7) + ((lane >> 4) << 3), bk = (lane >> 3) & 1;

    for (int i = tid; i < 128 * 136 * 2 / 16; i += 256) ((uint4*)Wt)[i] = ((const uint4*)g_wa1b)[i];
    uint32_t Ab = smem_u32(As) + ((mw * 32 + arow) * 136 + ak * 8) * 2;
    uint32_t Bb = smem_u32(Wt) + ((nw * 64 + brow) * 136 + bk * 8) * 2;

    for (int t = blockIdx.x; t < ntiles; t += gridDim.x) {
        int r0 = t * 128;
        #pragma unroll
        for (int c = 0; c < 16; c++) {
            int ci = c * 256 + tid;
            int m = ci >> 5, qq = ci & 31;
            int r = r0 + m;
            float4 v = {0.f, 0.f, 0.f, 0.f};
            if (r < N) v = ((const float4*)A)[(size_t)r * 32 + qq];
            uint2 pv = {pack_bf(v.x, v.y), pack_bf(v.z, v.w)};
            *(uint2*)((char*)As + (m * 136 + qq * 4) * 2) = pv;
        }
        __syncthreads();
        float acc[2][8][4];
        zero8(acc);
        wgemm<128, 136>(Ab, Bb, acc);
        #pragma unroll
        for (int mt = 0; mt < 2; mt++) {
            int rlo = r0 + mw * 32 + mt * 16 + g, rhi = rlo + 8;
            #pragma unroll
            for (int nt = 0; nt < 8; nt++) {
                int c0 = nw * 64 + nt * 8 + 2 * q;
                if (rlo < N) *(float2*)(g_x + (size_t)rlo * 128 + c0) = make_float2(acc[mt][nt][0], acc[mt][nt][1]);
                if (rhi < N) *(float2*)(g_x + (size_t)rhi * 128 + c0) = make_float2(acc[mt][nt][2], acc[mt][nt][3]);
            }
        }
        __syncthreads();
    }
}

// ---------------- Kernel 2: persistent bf16-MMA edge pipeline, 3 CTAs/SM ----------------
// smem bytes: W1 [0,16384) W2 [16384,49152) A1 [49152,57344) A2 [57344,73728)
//             b1s [73728) b2s [74240) i1s [74752) i2s [75008)  total 75264
#define EW1 0
#define EW2 16384
#define EA1 49152
#define EA2 57344
#define EB1 73728
#define EB2 74240
#define EI1 74752
#define EI2 75008
#define EDGE_SMEM 75264

__global__ __launch_bounds__(256, 3) void edge_mma_kernel(const float* __restrict__ ef,
                                                          const int* __restrict__ idx1,
                                                          const int* __restrict__ idx2,
                                                          const float* __restrict__ b1,
                                                          const float* __restrict__ b2,
                                                          int E, int ntiles) {
    extern __shared__ char smc[];
    float* b1s = (float*)(smc + EB1);
    float* b2s = (float*)(smc + EB2);
    int* i1s = (int*)(smc + EI1);
    int* i2s = (int*)(smc + EI2);

    int tid = threadIdx.x, wid = tid >> 5, lane = tid & 31;
    int g = lane >> 2, q = lane & 3;
    int mw = wid >> 2, nw = wid & 3;           // 2(m) x 4(n) warp grid, 32x32 tiles
    int arow_l = (lane & 7) + ((lane >> 3) & 1) * 8, ak = lane >> 4;
    int brow_l = (lane & 7) + ((lane >> 4) << 3), bk = (lane >> 3) & 1;
    const float4* ef4 = (const float4*)ef;

    uint32_t sb = smem_u32(smc);
    uint32_t W1u = sb + EW1, W2u = sb + EW2, A1u = sb + EA1, A2u = sb + EA2;

    // persistent weights / biases
    for (int i = tid; i < 16384 / 16; i += 256) ((uint4*)(smc + EW1))[i] = ((const uint4*)g_w1s)[i];
    for (int i = tid; i < 32768 / 16; i += 256) ((uint4*)(smc + EW2))[i] = ((const uint4*)g_w2s)[i];
    if (tid < 128) { b1s[tid] = b1[tid]; b2s[tid] = b2[tid]; }

    int arow = mw * 32 + arow_l;
    int brow0 = nw * 32 + brow_l;

    int t = blockIdx.x;
    if (t < ntiles) {
        int e0 = t * 64;
        #pragma unroll
        for (int c = 0; c < 4; c++) {
            int ci = c * 256 + tid;
            int m = ci >> 4, qq = ci & 15;
            int e = e0 + m;
            float4 v = {0.f, 0.f, 0.f, 0.f};
            if (e < E) v = ef4[(size_t)e * 16 + qq];
            uint2 pv = {pack_bf(v.x, v.y), pack_bf(v.z, v.w)};
            *(uint2*)(smc + EA1 + swz(m, qq >> 1, 128) + (qq & 1) * 8) = pv;
        }
        if (tid < 128) {
            int e = e0 + (tid & 63);
            int v = (e < E) ? ((tid < 64) ? idx1[e] : idx2[e]) : 0;
            if (tid < 64) i1s[tid] = v; else i2s[tid - 64] = v;
        }
    }
    __syncthreads();

    for (; t < ntiles; t += gridDim.x) {
        int e0 = t * 64;
        int tn = t + gridDim.x;
        bool have_next = tn < ntiles;

        // register-prefetch next tile
        float4 pf[4];
        int pidx = 0;
        if (have_next) {
            int ee0 = tn * 64;
            #pragma unroll
            for (int c = 0; c < 4; c++) {
                int ci = c * 256 + tid;
                int m = ci >> 4, qq = ci & 15;
                int e = ee0 + m;
                float4 v = {0.f, 0.f, 0.f, 0.f};
                if (e < E) v = ef4[(size_t)e * 16 + qq];
                pf[c] = v;
            }
            if (tid < 128) {
                int e = ee0 + (tid & 63);
                if (e < E) pidx = (tid < 64) ? idx1[e] : idx2[e];
            }
        }

        // ---- GEMM1: h = A1 @ W1^T (K=64) ----
        float acc[2][4][4];
        #pragma unroll
        for (int a = 0; a < 2; a++)
            #pragma unroll
            for (int b = 0; b < 4; b++)
                #pragma unroll
                for (int c = 0; c < 4; c++) acc[a][b][c] = 0.f;
        wgemm_sw<64, 128>(A1u, arow, ak, W1u, brow0, bk, acc);

        // ---- epilogue 1: A2 = bf16(sp(h + b1)), swizzled ----
        #pragma unroll
        for (int mt = 0; mt < 2; mt++) {
            int r = mw * 32 + mt * 16 + g;
            #pragma unroll
            for (int nt = 0; nt < 4; nt++) {
                int c0 = nw * 32 + nt * 8 + 2 * q;
                float2 bb = *(const float2*)(b1s + c0);
                uint32_t lo = pack_bf(sp_fast(acc[mt][nt][0] + bb.x), sp_fast(acc[mt][nt][1] + bb.y));
                uint32_t hi = pack_bf(sp_fast(acc[mt][nt][2] + bb.x), sp_fast(acc[mt][nt][3] + bb.y));
                int chunk = c0 >> 3, inner = (c0 & 7) * 2;
                *(uint32_t*)(smc + EA2 + swz(r, chunk, 256) + inner) = lo;
                *(uint32_t*)(smc + EA2 + swz(r + 8, chunk, 256) + inner) = hi;
            }
        }
        __syncthreads();

        // ---- GEMM2: W = A2 @ W2^T (K=128) ----
        #pragma unroll
        for (int a = 0; a < 2; a++)
            #pragma unroll
            for (int b = 0; b < 4; b++)
                #pragma unroll
                for (int c = 0; c < 4; c++) acc[a][b][c] = 0.f;
        wgemm_sw<128, 256>(A2u, arow, ak, W2u, brow0, bk, acc);

        // ---- epilogue 2: w=sp(acc+b2); v4-red scatter w * x[idx2] into sums[idx1] ----
        bool evn = (q & 1) == 0;
        #pragma unroll
        for (int mt = 0; mt < 2; mt++) {
            int rlo = mw * 32 + mt * 16 + g, rhi = rlo + 8;
            int elo = e0 + rlo, ehi = e0 + rhi;
            int n1lo = i1s[rlo], n2lo = i2s[rlo];
            int n1hi = i1s[rhi], n2hi = i2s[rhi];
            const float* xlo_p = g_x + (size_t)n2lo * 128;
            const float* xhi_p = g_x + (size_t)n2hi * 128;
            float* slo = g_sums + (size_t)n1lo * 128;
            float* shi = g_sums + (size_t)n1hi * 128;
            #pragma unroll
            for (int nt = 0; nt < 4; nt++) {
                int c0 = nw * 32 + nt * 8 + 2 * q;
                float2 bb = *(const float2*)(b2s + c0);
                float2 xl = *(const float2*)(xlo_p + c0);
                float2 xh = *(const float2*)(xhi_p + c0);
                float a0 = sp_fast(acc[mt][nt][0] + bb.x) * xl.x;
                float a1 = sp_fast(acc[mt][nt][1] + bb.y) * xl.y;
                float a2 = sp_fast(acc[mt][nt][2] + bb.x) * xh.x;
                float a3 = sp_fast(acc[mt][nt][3] + bb.y) * xh.y;
                float s0 = __shfl_xor_sync(0xffffffffu, evn ? a2 : a0, 1);
                float s1 = __shfl_xor_sync(0xffffffffu, evn ? a3 : a1, 1);
                int cb = nw * 32 + nt * 8 + 4 * (q >> 1);
                if (evn) {
                    if (elo < E)
                        asm volatile("red.global.add.v4.f32 [%0], {%1,%2,%3,%4};"
                                     :: "l"(slo + cb), "f"(a0), "f"(a1), "f"(s0), "f"(s1) : "memory");
                } else {
                    if (ehi < E)
                        asm volatile("red.global.add.v4.f32 [%0], {%1,%2,%3,%4};"
                                     :: "l"(shi + cb), "f"(s0), "f"(s1), "f"(a2), "f"(a3) : "memory");
                }
            }
            if (nw == 0 && q == 0) {
                if (elo < E) atomicAdd(&g_cnt[n1lo], 1.0f);
                if (ehi < E) atomicAdd(&g_cnt[n1hi], 1.0f);
            }
        }
        __syncthreads();

        // store prefetched next tile
        if (have_next) {
            #pragma unroll
            for (int c = 0; c < 4; c++) {
                int ci = c * 256 + tid;
                int m = ci >> 4, qq = ci & 15;
                uint2 pv = {pack_bf(pf[c].x, pf[c].y), pack_bf(pf[c].z, pf[c].w)};
                *(uint2*)(smc + EA1 + swz(m, qq >> 1, 128) + (qq & 1) * 8) = pv;
            }
            if (tid < 128) {
                if (tid < 64) i1s[tid] = pidx; else i2s[tid - 64] = pidx;
            }
        }
        __syncthreads();
    }
}

// ---------------- Kernel 3: node epilogue (bf16 MMA, persistent) ----------------
#define NODE_SMEM ((128 * 136 * 3) * 2 + 128 * 4 * 3)
__global__ __launch_bounds__(256, 2) void node_mma_kernel(const float* __restrict__ node_fea,
                                                          const float* __restrict__ baw2,
                                                          const float* __restrict__ baw3,
                                                          float* __restrict__ out,
                                                          int N, int ntiles) {
    extern __shared__ char smc[];
    __nv_bfloat16* W2t = (__nv_bfloat16*)smc;
    __nv_bfloat16* W3t = W2t + 128 * 136;
    __nv_bfloat16* As  = W3t + 128 * 136;
    float* inv = (float*)(As + 128 * 136);
    float* b2s = inv + 128;
    float* b3s = b2s + 128;

    int tid = threadIdx.x, wid = tid >> 5, lane = tid & 31;
    int g = lane >> 2, q = lane & 3;
    int mw = wid & 3, nw = wid >> 2;
    int arow = (lane & 7) + ((lane >> 3) & 1) * 8, ak = lane >> 4;
    int brow = (lane & 7) + ((lane >> 4) << 3), bk = (lane >> 3) & 1;

    for (int i = tid; i < 128 * 136 * 2 / 16; i += 256) {
        ((uint4*)W2t)[i] = ((const uint4*)g_wa2b)[i];
        ((uint4*)W3t)[i] = ((const uint4*)g_wa3b)[i];
    }
    if (tid < 128) { b2s[tid] = baw2[tid]; b3s[tid] = baw3[tid]; }

    uint32_t Ab = smem_u32(As) + ((mw * 32 + arow) * 136 + ak * 8) * 2;
    uint32_t B2b = smem_u32(W2t) + ((nw * 64 + brow) * 136 + bk * 8) * 2;
    uint32_t B3b = smem_u32(W3t) + ((nw * 64 + brow) * 136 + bk * 8) * 2;

    for (int t = blockIdx.x; t < ntiles; t += gridDim.x) {
        int r0 = t * 128;
        if (tid < 128) {
            int r = r0 + tid;
            inv[tid] = (r < N) ? 1.f / fmaxf(g_cnt[r], 1.f) : 0.f;
        }
        __syncthreads();
        #pragma unroll
        for (int c = 0; c < 16; c++) {
            int ci = c * 256 + tid;
            int m = ci >> 5, qq = ci & 31;
            int r = r0 + m;
            float4 v = {0.f, 0.f, 0.f, 0.f};
            if (r < N) v = ((const float4*)g_sums)[(size_t)r * 32 + qq];
            float iv = inv[m];
            uint2 pv = {pack_bf(v.x * iv, v.y * iv), pack_bf(v.z * iv, v.w * iv)};
            *(uint2*)((char*)As + (m * 136 + qq * 4) * 2) = pv;
        }
        __syncthreads();

        float acc[2][8][4];
        zero8(acc);
        wgemm<128, 136>(Ab, B2b, acc);

        uint32_t hlo[2][8], hhi[2][8];
        #pragma unroll
        for (int mt = 0; mt < 2; mt++)
            #pragma unroll
            for (int nt = 0; nt < 8; nt++) {
                int c0 = nw * 64 + nt * 8 + 2 * q;
                float2 bb = *(const float2*)(b2s + c0);
                hlo[mt][nt] = pack_bf(sp_fast(acc[mt][nt][0] + bb.x), sp_fast(acc[mt][nt][1] + bb.y));
                hhi[mt][nt] = pack_bf(sp_fast(acc[mt][nt][2] + bb.x), sp_fast(acc[mt][nt][3] + bb.y));
            }
        __syncthreads();
        #pragma unroll
        for (int mt = 0; mt < 2; mt++) {
            int r = mw * 32 + mt * 16 + g;
            #pragma unroll
            for (int nt = 0; nt < 8; nt++) {
                int c0 = nw * 64 + nt * 8 + 2 * q;
                *(uint32_t*)((char*)As + (r * 136 + c0) * 2) = hlo[mt][nt];
                *(uint32_t*)((char*)As + ((r + 8) * 136 + c0) * 2) = hhi[mt][nt];
            }
        }
        __syncthreads();

        zero8(acc);
        wgemm<128, 136>(Ab, B3b, acc);

        #pragma unroll
        for (int mt = 0; mt < 2; mt++) {
            int rlo = r0 + mw * 32 + mt * 16 + g, rhi = rlo + 8;
            #pragma unroll
            for (int nt = 0; nt < 8; nt++) {
                int c0 = nw * 64 + nt * 8 + 2 * q;
                float2 bb = *(const float2*)(b3s + c0);
                if (rlo < N) {
                    float2 nf = *(const float2*)(node_fea + (size_t)rlo * 128 + c0);
                    *(float2*)(out + (size_t)rlo * 128 + c0) =
                        make_float2(nf.x + acc[mt][nt][0] + bb.x, nf.y + acc[mt][nt][1] + bb.y);
                }
                if (rhi < N) {
                    float2 nf = *(const float2*)(node_fea + (size_t)rhi * 128 + c0);
                    *(float2*)(out + (size_t)rhi * 128 + c0) =
                        make_float2(nf.x + acc[mt][nt][2] + bb.x, nf.y + acc[mt][nt][3] + bb.y);
                }
            }
        }
        __syncthreads();
    }
}

extern "C" void kernel_launch(void* const* d_in, const int* in_sizes, int n_in,
                              void* d_out, int out_size) {
    const float* node_fea = (const float*)d_in[0];
    const int*   idx1     = (const int*)d_in[1];
    const int*   idx2     = (const int*)d_in[2];
    const float* edge_fea = (const float*)d_in[3];
    const float* W_aw1    = (const float*)d_in[4];
    const float* W_fg1    = (const float*)d_in[5];
    const float* b_fg1    = (const float*)d_in[6];
    const float* W_fg2    = (const float*)d_in[7];
    const float* b_fg2    = (const float*)d_in[8];
    const float* W_aw2    = (const float*)d_in[9];
    const float* b_aw2    = (const float*)d_in[10];
    const float* W_aw3    = (const float*)d_in[11];
    const float* b_aw3    = (const float*)d_in[12];

    int N = in_sizes[0] / 128;
    int E = in_sizes[1];
    float* out = (float*)d_out;

    void *p_sums, *p_cnt;
    cudaGetSymbolAddress(&p_sums, g_sums);
    cudaGetSymbolAddress(&p_cnt, g_cnt);
    cudaMemsetAsync(p_sums, 0, (size_t)N * 128 * sizeof(float));
    cudaMemsetAsync(p_cnt, 0, (size_t)N * sizeof(float));

    cudaFuncSetAttribute(gemm_x_mma, cudaFuncAttributeMaxDynamicSharedMemorySize, XK_SMEM);
    cudaFuncSetAttribute(edge_mma_kernel, cudaFuncAttributeMaxDynamicSharedMemorySize, EDGE_SMEM);
    cudaFuncSetAttribute(node_mma_kernel, cudaFuncAttributeMaxDynamicSharedMemorySize, NODE_SMEM);

    int ntN = (N + 127) / 128;
    int ntE = (E + 63) / 64;
    int gbN = ntN < 296 ? ntN : 296;
    int gbE = ntE < 444 ? ntE : 444;

    prep_weights<<<64, 256>>>(W_fg1, W_fg2, W_aw1, W_aw2, W_aw3);
    gemm_x_mma<<<gbN, 256, XK_SMEM>>>(node_fea, N, ntN);
    edge_mma_kernel<<<gbE, 256, EDGE_SMEM>>>(edge_fea, idx1, idx2, b_fg1, b_fg2, E, ntE);
    node_mma_kernel<<<gbN, 256, NODE_SMEM>>>(node_fea, b_aw2, b_aw3, out, N, ntN);
}

// round 7
// speedup vs baseline: 5.2729x; 1.0515x over previous
#include <cuda_runtime.h>
#include <cuda_bf16.h>
#include <math.h>
#include <stdint.h>

typedef unsigned long long u64;

#define NMAX 50000
#define EMAX 640000

// Scratch (static __device__ arrays per allocation rules)
__device__ float g_x[(size_t)NMAX * 128];
__device__ float g_sums[(size_t)NMAX * 128];
__device__ float g_cnt[NMAX];
// Edge-kernel weight images: XOR-swizzled, unpadded K-major [n][k] bf16
__device__ __align__(16) char g_w1s[128 * 128];   // W_fg1^T, K=64, 128B/row
__device__ __align__(16) char g_w2s[128 * 256];   // W_fg2^T, K=128, 256B/row
// Node/x kernels: padded (136) non-swizzled bf16 images
__device__ __align__(16) __nv_bfloat16 g_wa1b[128 * 136];
__device__ __align__(16) __nv_bfloat16 g_wa2b[128 * 136];
__device__ __align__(16) __nv_bfloat16 g_wa3b[128 * 136];

// fast softplus - ln2 via MUFU
__device__ __forceinline__ float sp_fast(float x) {
    float t = __expf(-fabsf(x));
    return fmaxf(x, 0.f) + __logf(1.f + t) - 0.69314718055994531f;
}
__device__ __forceinline__ uint32_t smem_u32(const void* p) {
    uint32_t a;
    asm("{ .reg .u64 t; cvta.to.shared.u64 t, %1; cvt.u32.u64 %0, t; }" : "=r"(a) : "l"(p));
    return a;
}
__device__ __forceinline__ void ldsm4(uint32_t& r0, uint32_t& r1, uint32_t& r2, uint32_t& r3, uint32_t addr) {
    asm volatile("ldmatrix.sync.aligned.m8n8.x4.shared.b16 {%0,%1,%2,%3}, [%4];"
                 : "=r"(r0), "=r"(r1), "=r"(r2), "=r"(r3) : "r"(addr));
}
__device__ __forceinline__ void mma16(float d[4], const uint32_t a[4], uint32_t b0, uint32_t b1) {
    asm("mma.sync.aligned.m16n8k16.row.col.f32.bf16.bf16.f32 "
        "{%0,%1,%2,%3}, {%4,%5,%6,%7}, {%8,%9}, {%0,%1,%2,%3};"
        : "+f"(d[0]), "+f"(d[1]), "+f"(d[2]), "+f"(d[3])
        : "r"(a[0]), "r"(a[1]), "r"(a[2]), "r"(a[3]), "r"(b0), "r"(b1));
}
__device__ __forceinline__ uint32_t pack_bf(float lo, float hi) {
    __nv_bfloat162 p = __floats2bfloat162_rn(lo, hi);
    return *(uint32_t*)&p;
}
// swizzled byte offset: 16B chunk index XORed with (row & 7)
__device__ __forceinline__ uint32_t swz(int row, int chunk, int RB) {
    return (uint32_t)(row * RB + (((chunk ^ (row & 7)) & (RB / 16 - 1)) << 4));
}

// ---- swizzled warp GEMM, 32(m) x 32(n) warp tile ----
template<int K, int RB>
__device__ __forceinline__ void wgemm_sw(uint32_t Au, int arow, int ak,
                                         uint32_t Bu, int brow0, int bk,
                                         float acc[2][4][4]) {
    #pragma unroll
    for (int kk = 0; kk < K; kk += 16) {
        int kc = kk >> 3;
        uint32_t a[2][4];
        #pragma unroll
        for (int mt = 0; mt < 2; mt++)
            ldsm4(a[mt][0], a[mt][1], a[mt][2], a[mt][3], Au + swz(arow + mt * 16, kc + ak, RB));
        #pragma unroll
        for (int p = 0; p < 2; p++) {
            uint32_t b0, b1, b2, b3;
            ldsm4(b0, b1, b2, b3, Bu + swz(brow0 + p * 16, kc + bk, RB));
            mma16(acc[0][2 * p], a[0], b0, b1);
            mma16(acc[1][2 * p], a[1], b0, b1);
            mma16(acc[0][2 * p + 1], a[0], b2, b3);
            mma16(acc[1][2 * p + 1], a[1], b2, b3);
        }
    }
}

// ---- padded non-swizzled warp GEMM (node / x kernels), 32x64 tile ----
__device__ __forceinline__ void zero8(float acc[2][8][4]) {
    #pragma unroll
    for (int a = 0; a < 2; a++)
        #pragma unroll
        for (int b = 0; b < 8; b++)
            #pragma unroll
            for (int c = 0; c < 4; c++) acc[a][b][c] = 0.f;
}
template<int K, int S>
__device__ __forceinline__ void wgemm(uint32_t Abase, uint32_t Bbase, float acc[2][8][4]) {
    #pragma unroll
    for (int kk = 0; kk < K; kk += 16) {
        uint32_t a[2][4];
        #pragma unroll
        for (int mt = 0; mt < 2; mt++)
            ldsm4(a[mt][0], a[mt][1], a[mt][2], a[mt][3], Abase + (mt * 16 * S + kk) * 2);
        #pragma unroll
        for (int p = 0; p < 4; p++) {
            uint32_t b0, b1, b2, b3;
            ldsm4(b0, b1, b2, b3, Bbase + (p * 16 * S + kk) * 2);
            mma16(acc[0][2 * p], a[0], b0, b1);
            mma16(acc[1][2 * p], a[1], b0, b1);
            mma16(acc[0][2 * p + 1], a[0], b2, b3);
            mma16(acc[1][2 * p + 1], a[1], b2, b3);
        }
    }
}

// ------------- prep: transpose + bf16 all weights -------------
__global__ void prep_weights(const float* __restrict__ W1, const float* __restrict__ W2,
                             const float* __restrict__ Wa1, const float* __restrict__ Wa2,
                             const float* __restrict__ Wa3) {
    int t = blockIdx.x * blockDim.x + threadIdx.x;
    int stride = blockDim.x * gridDim.x;
    for (int i = t; i < 64 * 128; i += stride) {
        int k = i >> 7, n = i & 127;
        *(__nv_bfloat16*)(g_w1s + swz(n, k >> 3, 128) + (k & 7) * 2) = __float2bfloat16(W1[i]);
    }
    for (int i = t; i < 128 * 128; i += stride) {
        int k = i >> 7, n = i & 127;
        *(__nv_bfloat16*)(g_w2s + swz(n, k >> 3, 256) + (k & 7) * 2) = __float2bfloat16(W2[i]);
        g_wa1b[n * 136 + k] = __float2bfloat16(Wa1[i]);
        g_wa2b[n * 136 + k] = __float2bfloat16(Wa2[i]);
        g_wa3b[n * 136 + k] = __float2bfloat16(Wa3[i]);
    }
}

// dummy no-op launch: shifts ncu capture index so -s 5 lands on the edge kernel
__global__ void dummy_kernel() {}

// ---------------- Kernel 1: x = node_fea @ W_aw1 (bf16 MMA, persistent) ----------------
#define XK_SMEM ((128 * 136 * 2) * 2)
__global__ __launch_bounds__(256, 2) void gemm_x_mma(const float* __restrict__ A,
                                                     int N, int ntiles) {
    extern __shared__ char smc[];
    __nv_bfloat16* Wt = (__nv_bfloat16*)smc;
    __nv_bfloat16* As = Wt + 128 * 136;
    int tid = threadIdx.x, wid = tid >> 5, lane = tid & 31;
    int g = lane >> 2, q = lane & 3;
    int mw = wid & 3, nw = wid >> 2;
    int arow = (lane & 7) + ((lane >> 3) & 1) * 8, ak = lane >> 4;
    int brow = (lane & 7) + ((lane >> 4) << 3), bk = (lane >> 3) & 1;

    for (int i = tid; i < 128 * 136 * 2 / 16; i += 256) ((uint4*)Wt)[i] = ((const uint4*)g_wa1b)[i];
    uint32_t Ab = smem_u32(As) + ((mw * 32 + arow) * 136 + ak * 8) * 2;
    uint32_t Bb = smem_u32(Wt) + ((nw * 64 + brow) * 136 + bk * 8) * 2;

    for (int t = blockIdx.x; t < ntiles; t += gridDim.x) {
        int r0 = t * 128;
        #pragma unroll
        for (int c = 0; c < 16; c++) {
            int ci = c * 256 + tid;
            int m = ci >> 5, qq = ci & 31;
            int r = r0 + m;
            float4 v = {0.f, 0.f, 0.f, 0.f};
            if (r < N) v = ((const float4*)A)[(size_t)r * 32 + qq];
            uint2 pv = {pack_bf(v.x, v.y), pack_bf(v.z, v.w)};
            *(uint2*)((char*)As + (m * 136 + qq * 4) * 2) = pv;
        }
        __syncthreads();
        float acc[2][8][4];
        zero8(acc);
        wgemm<128, 136>(Ab, Bb, acc);
        #pragma unroll
        for (int mt = 0; mt < 2; mt++) {
            int rlo = r0 + mw * 32 + mt * 16 + g, rhi = rlo + 8;
            #pragma unroll
            for (int nt = 0; nt < 8; nt++) {
                int c0 = nw * 64 + nt * 8 + 2 * q;
                if (rlo < N) *(float2*)(g_x + (size_t)rlo * 128 + c0) = make_float2(acc[mt][nt][0], acc[mt][nt][1]);
                if (rhi < N) *(float2*)(g_x + (size_t)rhi * 128 + c0) = make_float2(acc[mt][nt][2], acc[mt][nt][3]);
            }
        }
        __syncthreads();
    }
}

// ---------------- Kernel 2: persistent bf16-MMA edge pipeline ----------------
// smem bytes: W1 [0,16384) W2 [16384,49152) A1 [49152,57344) A2 [57344,73728)
//             b1s [73728) b2s [74240) i1s [74752) i2s [75008)  total 75264
#define EW1 0
#define EW2 16384
#define EA1 49152
#define EA2 57344
#define EB1 73728
#define EB2 74240
#define EI1 74752
#define EI2 75008
#define EDGE_SMEM 75264

__global__ __launch_bounds__(256, 2) void edge_mma_kernel(const float* __restrict__ ef,
                                                          const int* __restrict__ idx1,
                                                          const int* __restrict__ idx2,
                                                          const float* __restrict__ b1,
                                                          const float* __restrict__ b2,
                                                          int E, int ntiles) {
    extern __shared__ char smc[];
    float* b1s = (float*)(smc + EB1);
    float* b2s = (float*)(smc + EB2);
    int* i1s = (int*)(smc + EI1);
    int* i2s = (int*)(smc + EI2);

    int tid = threadIdx.x, wid = tid >> 5, lane = tid & 31;
    int g = lane >> 2, q = lane & 3;
    int mw = wid >> 2, nw = wid & 3;           // 2(m) x 4(n) warp grid, 32x32 tiles
    int arow_l = (lane & 7) + ((lane >> 3) & 1) * 8, ak = lane >> 4;
    int brow_l = (lane & 7) + ((lane >> 4) << 3), bk = (lane >> 3) & 1;
    const float4* ef4 = (const float4*)ef;

    uint32_t sb = smem_u32(smc);
    uint32_t W1u = sb + EW1, W2u = sb + EW2, A1u = sb + EA1, A2u = sb + EA2;

    // persistent weights / biases
    for (int i = tid; i < 16384 / 16; i += 256) ((uint4*)(smc + EW1))[i] = ((const uint4*)g_w1s)[i];
    for (int i = tid; i < 32768 / 16; i += 256) ((uint4*)(smc + EW2))[i] = ((const uint4*)g_w2s)[i];
    if (tid < 128) { b1s[tid] = b1[tid]; b2s[tid] = b2[tid]; }

    int arow = mw * 32 + arow_l;
    int brow0 = nw * 32 + brow_l;

    int t = blockIdx.x;
    if (t < ntiles) {
        int e0 = t * 64;
        #pragma unroll
        for (int c = 0; c < 4; c++) {
            int ci = c * 256 + tid;
            int m = ci >> 4, qq = ci & 15;
            int e = e0 + m;
            float4 v = {0.f, 0.f, 0.f, 0.f};
            if (e < E) v = ef4[(size_t)e * 16 + qq];
            uint2 pv = {pack_bf(v.x, v.y), pack_bf(v.z, v.w)};
            *(uint2*)(smc + EA1 + swz(m, qq >> 1, 128) + (qq & 1) * 8) = pv;
        }
        if (tid < 128) {
            int e = e0 + (tid & 63);
            int v = (e < E) ? ((tid < 64) ? idx1[e] : idx2[e]) : 0;
            if (tid < 64) i1s[tid] = v; else i2s[tid - 64] = v;
        }
    }
    __syncthreads();

    for (; t < ntiles; t += gridDim.x) {
        int e0 = t * 64;
        int tn = t + gridDim.x;
        bool have_next = tn < ntiles;

        // current-tile scatter/gather indices (stable in smem for this iteration)
        int n1c[2][2], n2c[2][2];
        #pragma unroll
        for (int mt = 0; mt < 2; mt++) {
            int rlo = mw * 32 + mt * 16 + g;
            n1c[mt][0] = i1s[rlo]; n1c[mt][1] = i1s[rlo + 8];
            n2c[mt][0] = i2s[rlo]; n2c[mt][1] = i2s[rlo + 8];
        }
        // x-gather prefetch: issue all 16 LDG.64 now; they land during the two GEMMs
        float2 xg[2][2][4];
        #pragma unroll
        for (int mt = 0; mt < 2; mt++)
            #pragma unroll
            for (int rr = 0; rr < 2; rr++) {
                const float* xr = g_x + (size_t)n2c[mt][rr] * 128;
                #pragma unroll
                for (int nt = 0; nt < 4; nt++)
                    xg[mt][rr][nt] = *(const float2*)(xr + nw * 32 + nt * 8 + 2 * q);
            }

        // register-prefetch next tile's edge features + indices
        float4 pf[4];
        int pidx = 0;
        if (have_next) {
            int ee0 = tn * 64;
            #pragma unroll
            for (int c = 0; c < 4; c++) {
                int ci = c * 256 + tid;
                int m = ci >> 4, qq = ci & 15;
                int e = ee0 + m;
                float4 v = {0.f, 0.f, 0.f, 0.f};
                if (e < E) v = ef4[(size_t)e * 16 + qq];
                pf[c] = v;
            }
            if (tid < 128) {
                int e = ee0 + (tid & 63);
                if (e < E) pidx = (tid < 64) ? idx1[e] : idx2[e];
            }
        }

        // ---- GEMM1: h = A1 @ W1^T (K=64) ----
        float acc[2][4][4];
        #pragma unroll
        for (int a = 0; a < 2; a++)
            #pragma unroll
            for (int b = 0; b < 4; b++)
                #pragma unroll
                for (int c = 0; c < 4; c++) acc[a][b][c] = 0.f;
        wgemm_sw<64, 128>(A1u, arow, ak, W1u, brow0, bk, acc);

        // ---- epilogue 1: A2 = bf16(sp(h + b1)), swizzled ----
        #pragma unroll
        for (int mt = 0; mt < 2; mt++) {
            int r = mw * 32 + mt * 16 + g;
            #pragma unroll
            for (int nt = 0; nt < 4; nt++) {
                int c0 = nw * 32 + nt * 8 + 2 * q;
                float2 bb = *(const float2*)(b1s + c0);
                uint32_t lo = pack_bf(sp_fast(acc[mt][nt][0] + bb.x), sp_fast(acc[mt][nt][1] + bb.y));
                uint32_t hi = pack_bf(sp_fast(acc[mt][nt][2] + bb.x), sp_fast(acc[mt][nt][3] + bb.y));
                int chunk = c0 >> 3, inner = (c0 & 7) * 2;
                *(uint32_t*)(smc + EA2 + swz(r, chunk, 256) + inner) = lo;
                *(uint32_t*)(smc + EA2 + swz(r + 8, chunk, 256) + inner) = hi;
            }
        }
        __syncthreads();

        // ---- GEMM2: W = A2 @ W2^T (K=128) ----
        #pragma unroll
        for (int a = 0; a < 2; a++)
            #pragma unroll
            for (int b = 0; b < 4; b++)
                #pragma unroll
                for (int c = 0; c < 4; c++) acc[a][b][c] = 0.f;
        wgemm_sw<128, 256>(A2u, arow, ak, W2u, brow0, bk, acc);

        // ---- epilogue 2: w=sp(acc+b2); v4-red scatter w * xg into sums[idx1] ----
        bool evn = (q & 1) == 0;
        #pragma unroll
        for (int mt = 0; mt < 2; mt++) {
            int rlo = mw * 32 + mt * 16 + g, rhi = rlo + 8;
            int elo = e0 + rlo, ehi = e0 + rhi;
            float* slo = g_sums + (size_t)n1c[mt][0] * 128;
            float* shi = g_sums + (size_t)n1c[mt][1] * 128;
            #pragma unroll
            for (int nt = 0; nt < 4; nt++) {
                int c0 = nw * 32 + nt * 8 + 2 * q;
                float2 bb = *(const float2*)(b2s + c0);
                float2 xl = xg[mt][0][nt];
                float2 xh = xg[mt][1][nt];
                float a0 = sp_fast(acc[mt][nt][0] + bb.x) * xl.x;
                float a1 = sp_fast(acc[mt][nt][1] + bb.y) * xl.y;
                float a2 = sp_fast(acc[mt][nt][2] + bb.x) * xh.x;
                float a3 = sp_fast(acc[mt][nt][3] + bb.y) * xh.y;
                float s0 = __shfl_xor_sync(0xffffffffu, evn ? a2 : a0, 1);
                float s1 = __shfl_xor_sync(0xffffffffu, evn ? a3 : a1, 1);
                int cb = nw * 32 + nt * 8 + 4 * (q >> 1);
                if (evn) {
                    if (elo < E)
                        asm volatile("red.global.add.v4.f32 [%0], {%1,%2,%3,%4};"
                                     :: "l"(slo + cb), "f"(a0), "f"(a1), "f"(s0), "f"(s1) : "memory");
                } else {
                    if (ehi < E)
                        asm volatile("red.global.add.v4.f32 [%0], {%1,%2,%3,%4};"
                                     :: "l"(shi + cb), "f"(s0), "f"(s1), "f"(a2), "f"(a3) : "memory");
                }
            }
            if (nw == 0 && q == 0) {
                if (elo < E) atomicAdd(&g_cnt[n1c[mt][0]], 1.0f);
                if (ehi < E) atomicAdd(&g_cnt[n1c[mt][1]], 1.0f);
            }
        }
        __syncthreads();

        // store prefetched next tile
        if (have_next) {
            #pragma unroll
            for (int c = 0; c < 4; c++) {
                int ci = c * 256 + tid;
                int m = ci >> 4, qq = ci & 15;
                uint2 pv = {pack_bf(pf[c].x, pf[c].y), pack_bf(pf[c].z, pf[c].w)};
                *(uint2*)(smc + EA1 + swz(m, qq >> 1, 128) + (qq & 1) * 8) = pv;
            }
            if (tid < 128) {
                if (tid < 64) i1s[tid] = pidx; else i2s[tid - 64] = pidx;
            }
        }
        __syncthreads();
    }
}

// ---------------- Kernel 3: node epilogue (bf16 MMA, persistent) ----------------
#define NODE_SMEM ((128 * 136 * 3) * 2 + 128 * 4 * 3)
__global__ __launch_bounds__(256, 2) void node_mma_kernel(const float* __restrict__ node_fea,
                                                          const float* __restrict__ baw2,
                                                          const float* __restrict__ baw3,
                                                          float* __restrict__ out,
                                                          int N, int ntiles) {
    extern __shared__ char smc[];
    __nv_bfloat16* W2t = (__nv_bfloat16*)smc;
    __nv_bfloat16* W3t = W2t + 128 * 136;
    __nv_bfloat16* As  = W3t + 128 * 136;
    float* inv = (float*)(As + 128 * 136);
    float* b2s = inv + 128;
    float* b3s = b2s + 128;

    int tid = threadIdx.x, wid = tid >> 5, lane = tid & 31;
    int g = lane >> 2, q = lane & 3;
    int mw = wid & 3, nw = wid >> 2;
    int arow = (lane & 7) + ((lane >> 3) & 1) * 8, ak = lane >> 4;
    int brow = (lane & 7) + ((lane >> 4) << 3), bk = (lane >> 3) & 1;

    for (int i = tid; i < 128 * 136 * 2 / 16; i += 256) {
        ((uint4*)W2t)[i] = ((const uint4*)g_wa2b)[i];
        ((uint4*)W3t)[i] = ((const uint4*)g_wa3b)[i];
    }
    if (tid < 128) { b2s[tid] = baw2[tid]; b3s[tid] = baw3[tid]; }

    uint32_t Ab = smem_u32(As) + ((mw * 32 + arow) * 136 + ak * 8) * 2;
    uint32_t B2b = smem_u32(W2t) + ((nw * 64 + brow) * 136 + bk * 8) * 2;
    uint32_t B3b = smem_u32(W3t) + ((nw * 64 + brow) * 136 + bk * 8) * 2;

    for (int t = blockIdx.x; t < ntiles; t += gridDim.x) {
        int r0 = t * 128;
        if (tid < 128) {
            int r = r0 + tid;
            inv[tid] = (r < N) ? 1.f / fmaxf(g_cnt[r], 1.f) : 0.f;
        }
        __syncthreads();
        #pragma unroll
        for (int c = 0; c < 16; c++) {
            int ci = c * 256 + tid;
            int m = ci >> 5, qq = ci & 31;
            int r = r0 + m;
            float4 v = {0.f, 0.f, 0.f, 0.f};
            if (r < N) v = ((const float4*)g_sums)[(size_t)r * 32 + qq];
            float iv = inv[m];
            uint2 pv = {pack_bf(v.x * iv, v.y * iv), pack_bf(v.z * iv, v.w * iv)};
            *(uint2*)((char*)As + (m * 136 + qq * 4) * 2) = pv;
        }
        __syncthreads();

        float acc[2][8][4];
        zero8(acc);
        wgemm<128, 136>(Ab, B2b, acc);

        uint32_t hlo[2][8], hhi[2][8];
        #pragma unroll
        for (int mt = 0; mt < 2; mt++)
            #pragma unroll
            for (int nt = 0; nt < 8; nt++) {
                int c0 = nw * 64 + nt * 8 + 2 * q;
                float2 bb = *(const float2*)(b2s + c0);
                hlo[mt][nt] = pack_bf(sp_fast(acc[mt][nt][0] + bb.x), sp_fast(acc[mt][nt][1] + bb.y));
                hhi[mt][nt] = pack_bf(sp_fast(acc[mt][nt][2] + bb.x), sp_fast(acc[mt][nt][3] + bb.y));
            }
        __syncthreads();
        #pragma unroll
        for (int mt = 0; mt < 2; mt++) {
            int r = mw * 32 + mt * 16 + g;
            #pragma unroll
            for (int nt = 0; nt < 8; nt++) {
                int c0 = nw * 64 + nt * 8 + 2 * q;
                *(uint32_t*)((char*)As + (r * 136 + c0) * 2) = hlo[mt][nt];
                *(uint32_t*)((char*)As + ((r + 8) * 136 + c0) * 2) = hhi[mt][nt];
            }
        }
        __syncthreads();

        zero8(acc);
        wgemm<128, 136>(Ab, B3b, acc);

        #pragma unroll
        for (int mt = 0; mt < 2; mt++) {
            int rlo = r0 + mw * 32 + mt * 16 + g, rhi = rlo + 8;
            #pragma unroll
            for (int nt = 0; nt < 8; nt++) {
                int c0 = nw * 64 + nt * 8 + 2 * q;
                float2 bb = *(const float2*)(b3s + c0);
                if (rlo < N) {
                    float2 nf = *(const float2*)(node_fea + (size_t)rlo * 128 + c0);
                    *(float2*)(out + (size_t)rlo * 128 + c0) =
                        make_float2(nf.x + acc[mt][nt][0] + bb.x, nf.y + acc[mt][nt][1] + bb.y);
                }
                if (rhi < N) {
                    float2 nf = *(const float2*)(node_fea + (size_t)rhi * 128 + c0);
                    *(float2*)(out + (size_t)rhi * 128 + c0) =
                        make_float2(nf.x + acc[mt][nt][2] + bb.x, nf.y + acc[mt][nt][3] + bb.y);
                }
            }
        }
        __syncthreads();
    }
}

extern "C" void kernel_launch(void* const* d_in, const int* in_sizes, int n_in,
                              void* d_out, int out_size) {
    const float* node_fea = (const float*)d_in[0];
    const int*   idx1     = (const int*)d_in[1];
    const int*   idx2     = (const int*)d_in[2];
    const float* edge_fea = (const float*)d_in[3];
    const float* W_aw1    = (const float*)d_in[4];
    const float* W_fg1    = (const float*)d_in[5];
    const float* b_fg1    = (const float*)d_in[6];
    const float* W_fg2    = (const float*)d_in[7];
    const float* b_fg2    = (const float*)d_in[8];
    const float* W_aw2    = (const float*)d_in[9];
    const float* b_aw2    = (const float*)d_in[10];
    const float* W_aw3    = (const float*)d_in[11];
    const float* b_aw3    = (const float*)d_in[12];

    int N = in_sizes[0] / 128;
    int E = in_sizes[1];
    float* out = (float*)d_out;

    void *p_sums, *p_cnt;
    cudaGetSymbolAddress(&p_sums, g_sums);
    cudaGetSymbolAddress(&p_cnt, g_cnt);
    cudaMemsetAsync(p_sums, 0, (size_t)N * 128 * sizeof(float));
    cudaMemsetAsync(p_cnt, 0, (size_t)N * sizeof(float));

    cudaFuncSetAttribute(gemm_x_mma, cudaFuncAttributeMaxDynamicSharedMemorySize, XK_SMEM);
    cudaFuncSetAttribute(edge_mma_kernel, cudaFuncAttributeMaxDynamicSharedMemorySize, EDGE_SMEM);
    cudaFuncSetAttribute(node_mma_kernel, cudaFuncAttributeMaxDynamicSharedMemorySize, NODE_SMEM);

    int ntN = (N + 127) / 128;
    int ntE = (E + 63) / 64;
    int gbN = ntN < 296 ? ntN : 296;
    int gbE = ntE < 296 ? ntE : 296;

    prep_weights<<<64, 256>>>(W_fg1, W_fg2, W_aw1, W_aw2, W_aw3);
    dummy_kernel<<<1, 32>>>();   // shifts ncu -s 5 capture onto edge_mma_kernel
    gemm_x_mma<<<gbN, 256, XK_SMEM>>>(node_fea, N, ntN);
    edge_mma_kernel<<<gbE, 256, EDGE_SMEM>>>(edge_fea, idx1, idx2, b_fg1, b_fg2, E, ntE);
    node_mma_kernel<<<gbN, 256, NODE_SMEM>>>(node_fea, b_aw2, b_aw3, out, N, ntN);
}

// round 8
// speedup vs baseline: 5.5955x; 1.0612x over previous
#include <cuda_runtime.h>
#include <cuda_bf16.h>
#include <math.h>
#include <stdint.h>

typedef unsigned long long u64;

#define NMAX 50000
#define EMAX 640000

__device__ float g_x[(size_t)NMAX * 128];
__device__ float g_sums[(size_t)NMAX * 128];
__device__ float g_cnt[NMAX];
__device__ __align__(16) char g_w1s[128 * 128];   // W_fg1^T, K=64, 128B/row, swizzled
__device__ __align__(16) char g_w2s[128 * 256];   // W_fg2^T, K=128, 256B/row, swizzled
__device__ __align__(16) __nv_bfloat16 g_wa1b[128 * 136];
__device__ __align__(16) __nv_bfloat16 g_wa2b[128 * 136];
__device__ __align__(16) __nv_bfloat16 g_wa3b[128 * 136];

__device__ __forceinline__ float sp_fast(float x) {
    float t = __expf(-fabsf(x));
    return fmaxf(x, 0.f) + __logf(1.f + t) - 0.69314718055994531f;
}
__device__ __forceinline__ uint32_t smem_u32(const void* p) {
    uint32_t a;
    asm("{ .reg .u64 t; cvta.to.shared.u64 t, %1; cvt.u32.u64 %0, t; }" : "=r"(a) : "l"(p));
    return a;
}
__device__ __forceinline__ void ldsm4(uint32_t& r0, uint32_t& r1, uint32_t& r2, uint32_t& r3, uint32_t addr) {
    asm volatile("ldmatrix.sync.aligned.m8n8.x4.shared.b16 {%0,%1,%2,%3}, [%4];"
                 : "=r"(r0), "=r"(r1), "=r"(r2), "=r"(r3) : "r"(addr));
}
__device__ __forceinline__ void mma16(float d[4], const uint32_t a[4], uint32_t b0, uint32_t b1) {
    asm("mma.sync.aligned.m16n8k16.row.col.f32.bf16.bf16.f32 "
        "{%0,%1,%2,%3}, {%4,%5,%6,%7}, {%8,%9}, {%0,%1,%2,%3};"
        : "+f"(d[0]), "+f"(d[1]), "+f"(d[2]), "+f"(d[3])
        : "r"(a[0]), "r"(a[1]), "r"(a[2]), "r"(a[3]), "r"(b0), "r"(b1));
}
__device__ __forceinline__ uint32_t pack_bf(float lo, float hi) {
    __nv_bfloat162 p = __floats2bfloat162_rn(lo, hi);
    return *(uint32_t*)&p;
}
__device__ __forceinline__ uint32_t swz2(int row, int chunk, int RB) {
    return (uint32_t)(row * RB + (((chunk ^ (row & 7)) & (RB / 16 - 1)) << 4));
}

// ---- swizzled warp GEMM, 32(m) x 32(n) warp tile ----
template<int K, int RB>
__device__ __forceinline__ void wgemm_sw(uint32_t Au, int arow, int ak,
                                         uint32_t Bu, int brow0, int bk,
                                         float acc[2][4][4]) {
    #pragma unroll
    for (int kk = 0; kk < K; kk += 16) {
        int kc = kk >> 3;
        uint32_t a[2][4];
        #pragma unroll
        for (int mt = 0; mt < 2; mt++)
            ldsm4(a[mt][0], a[mt][1], a[mt][2], a[mt][3], Au + swz2(arow + mt * 16, kc + ak, RB));
        #pragma unroll
        for (int p = 0; p < 2; p++) {
            uint32_t b0, b1, b2, b3;
            ldsm4(b0, b1, b2, b3, Bu + swz2(brow0 + p * 16, kc + bk, RB));
            mma16(acc[0][2 * p], a[0], b0, b1);
            mma16(acc[1][2 * p], a[1], b0, b1);
            mma16(acc[0][2 * p + 1], a[0], b2, b3);
            mma16(acc[1][2 * p + 1], a[1], b2, b3);
        }
    }
}

__device__ __forceinline__ void zero8(float acc[2][8][4]) {
    #pragma unroll
    for (int a = 0; a < 2; a++)
        #pragma unroll
        for (int b = 0; b < 8; b++)
            #pragma unroll
            for (int c = 0; c < 4; c++) acc[a][b][c] = 0.f;
}
template<int K, int S>
__device__ __forceinline__ void wgemm(uint32_t Abase, uint32_t Bbase, float acc[2][8][4]) {
    #pragma unroll
    for (int kk = 0; kk < K; kk += 16) {
        uint32_t a[2][4];
        #pragma unroll
        for (int mt = 0; mt < 2; mt++)
            ldsm4(a[mt][0], a[mt][1], a[mt][2], a[mt][3], Abase + (mt * 16 * S + kk) * 2);
        #pragma unroll
        for (int p = 0; p < 4; p++) {
            uint32_t b0, b1, b2, b3;
            ldsm4(b0, b1, b2, b3, Bbase + (p * 16 * S + kk) * 2);
            mma16(acc[0][2 * p], a[0], b0, b1);
            mma16(acc[1][2 * p], a[1], b0, b1);
            mma16(acc[0][2 * p + 1], a[0], b2, b3);
            mma16(acc[1][2 * p + 1], a[1], b2, b3);
        }
    }
}

__global__ void prep_weights(const float* __restrict__ W1, const float* __restrict__ W2,
                             const float* __restrict__ Wa1, const float* __restrict__ Wa2,
                             const float* __restrict__ Wa3) {
    int t = blockIdx.x * blockDim.x + threadIdx.x;
    int stride = blockDim.x * gridDim.x;
    for (int i = t; i < 64 * 128; i += stride) {
        int k = i >> 7, n = i & 127;
        *(__nv_bfloat16*)(g_w1s + swz2(n, k >> 3, 128) + (k & 7) * 2) = __float2bfloat16(W1[i]);
    }
    for (int i = t; i < 128 * 128; i += stride) {
        int k = i >> 7, n = i & 127;
        *(__nv_bfloat16*)(g_w2s + swz2(n, k >> 3, 256) + (k & 7) * 2) = __float2bfloat16(W2[i]);
        g_wa1b[n * 136 + k] = __float2bfloat16(Wa1[i]);
        g_wa2b[n * 136 + k] = __float2bfloat16(Wa2[i]);
        g_wa3b[n * 136 + k] = __float2bfloat16(Wa3[i]);
    }
}

__global__ void dummy_kernel() {}

#define XK_SMEM ((128 * 136 * 2) * 2)
__global__ __launch_bounds__(256, 2) void gemm_x_mma(const float* __restrict__ A,
                                                     int N, int ntiles) {
    extern __shared__ char smc[];
    __nv_bfloat16* Wt = (__nv_bfloat16*)smc;
    __nv_bfloat16* As = Wt + 128 * 136;
    int tid = threadIdx.x, wid = tid >> 5, lane = tid & 31;
    int g = lane >> 2, q = lane & 3;
    int mw = wid & 3, nw = wid >> 2;
    int arow = (lane & 7) + ((lane >> 3) & 1) * 8, ak = lane >> 4;
    int brow = (lane & 7) + ((lane >> 4) << 3), bk = (lane >> 3) & 1;

    for (int i = tid; i < 128 * 136 * 2 / 16; i += 256) ((uint4*)Wt)[i] = ((const uint4*)g_wa1b)[i];
    uint32_t Ab = smem_u32(As) + ((mw * 32 + arow) * 136 + ak * 8) * 2;
    uint32_t Bb = smem_u32(Wt) + ((nw * 64 + brow) * 136 + bk * 8) * 2;

    for (int t = blockIdx.x; t < ntiles; t += gridDim.x) {
        int r0 = t * 128;
        #pragma unroll
        for (int c = 0; c < 16; c++) {
            int ci = c * 256 + tid;
            int m = ci >> 5, qq = ci & 31;
            int r = r0 + m;
            float4 v = {0.f, 0.f, 0.f, 0.f};
            if (r < N) v = ((const float4*)A)[(size_t)r * 32 + qq];
            uint2 pv = {pack_bf(v.x, v.y), pack_bf(v.z, v.w)};
            *(uint2*)((char*)As + (m * 136 + qq * 4) * 2) = pv;
        }
        __syncthreads();
        float acc[2][8][4];
        zero8(acc);
        wgemm<128, 136>(Ab, Bb, acc);
        #pragma unroll
        for (int mt = 0; mt < 2; mt++) {
            int rlo = r0 + mw * 32 + mt * 16 + g, rhi = rlo + 8;
            #pragma unroll
            for (int nt = 0; nt < 8; nt++) {
                int c0 = nw * 64 + nt * 8 + 2 * q;
                if (rlo < N) *(float2*)(g_x + (size_t)rlo * 128 + c0) = make_float2(acc[mt][nt][0], acc[mt][nt][1]);
                if (rhi < N) *(float2*)(g_x + (size_t)rhi * 128 + c0) = make_float2(acc[mt][nt][2], acc[mt][nt][3]);
            }
        }
        __syncthreads();
    }
}

// ---------------- Kernel 2: persistent bf16-MMA edge pipeline ----------------
#define EW1 0
#define EW2 16384
#define EA1 49152
#define EA2 57344
#define EP  73728
#define EB1 106496
#define EB2 107008
#define EI1 107520
#define EI2 107776
#define EDGE_SMEM 108032

__global__ __launch_bounds__(256, 2) void edge_mma_kernel(const float* __restrict__ ef,
                                                          const int* __restrict__ idx1,
                                                          const int* __restrict__ idx2,
                                                          const float* __restrict__ b1,
                                                          const float* __restrict__ b2,
                                                          int E, int ntiles) {
    extern __shared__ char smc[];
    float* b1s = (float*)(smc + EB1);
    float* b2s = (float*)(smc + EB2);
    int* i1s = (int*)(smc + EI1);
    int* i2s = (int*)(smc + EI2);

    int tid = threadIdx.x, wid = tid >> 5, lane = tid & 31;
    int g = lane >> 2, q = lane & 3;
    int mw = wid >> 2, nw = wid & 3;
    int arow_l = (lane & 7) + ((lane >> 3) & 1) * 8, ak = lane >> 4;
    int brow_l = (lane & 7) + ((lane >> 4) << 3), bk = (lane >> 3) & 1;
    const float4* ef4 = (const float4*)ef;

    uint32_t sb = smem_u32(smc);
    uint32_t W1u = sb + EW1, W2u = sb + EW2, A1u = sb + EA1, A2u = sb + EA2;

    for (int i = tid; i < 16384 / 16; i += 256) ((uint4*)(smc + EW1))[i] = ((const uint4*)g_w1s)[i];
    for (int i = tid; i < 32768 / 16; i += 256) ((uint4*)(smc + EW2))[i] = ((const uint4*)g_w2s)[i];
    if (tid < 128) { b1s[tid] = b1[tid]; b2s[tid] = b2[tid]; }

    int arow = mw * 32 + arow_l;
    int brow0 = nw * 32 + brow_l;

    int t = blockIdx.x;
    if (t < ntiles) {
        int e0 = t * 64;
        #pragma unroll
        for (int c = 0; c < 4; c++) {
            int ci = c * 256 + tid;
            int m = ci >> 4, qq = ci & 15;
            int e = e0 + m;
            float4 v = {0.f, 0.f, 0.f, 0.f};
            if (e < E) v = ef4[(size_t)e * 16 + qq];
            uint2 pv = {pack_bf(v.x, v.y), pack_bf(v.z, v.w)};
            *(uint2*)(smc + EA1 + swz2(m, qq >> 1, 128) + (qq & 1) * 8) = pv;
        }
        if (tid < 128) {
            int e = e0 + (tid & 63);
            int v = (e < E) ? ((tid < 64) ? idx1[e] : idx2[e]) : 0;
            if (tid < 64) i1s[tid] = v; else i2s[tid - 64] = v;
        }
    }
    __syncthreads();

    for (; t < ntiles; t += gridDim.x) {
        int e0 = t * 64;
        int tn = t + gridDim.x;
        bool have_next = tn < ntiles;

        // row-coalesced x-gather prefetch: warp owns edges wid*8..wid*8+7
        float4 xg[8];
        int n1r[8];
        #pragma unroll
        for (int j = 0; j < 8; j++) {
            int r = wid * 8 + j;
            int n2 = i2s[r];
            n1r[j] = i1s[r];
            xg[j] = *(const float4*)(g_x + (size_t)n2 * 128 + lane * 4);
        }

        // register-prefetch next tile's edge features + indices
        float4 pf[4];
        int pidx = 0;
        if (have_next) {
            int ee0 = tn * 64;
            #pragma unroll
            for (int c = 0; c < 4; c++) {
                int ci = c * 256 + tid;
                int m = ci >> 4, qq = ci & 15;
                int e = ee0 + m;
                float4 v = {0.f, 0.f, 0.f, 0.f};
                if (e < E) v = ef4[(size_t)e * 16 + qq];
                pf[c] = v;
            }
            if (tid < 128) {
                int e = ee0 + (tid & 63);
                if (e < E) pidx = (tid < 64) ? idx1[e] : idx2[e];
            }
        }

        // ---- GEMM1 ----
        float acc[2][4][4];
        #pragma unroll
        for (int a = 0; a < 2; a++)
            #pragma unroll
            for (int b = 0; b < 4; b++)
                #pragma unroll
                for (int c = 0; c < 4; c++) acc[a][b][c] = 0.f;
        wgemm_sw<64, 128>(A1u, arow, ak, W1u, brow0, bk, acc);

        // ---- epilogue 1: A2 = bf16(sp(h + b1)) ----
        #pragma unroll
        for (int mt = 0; mt < 2; mt++) {
            int r = mw * 32 + mt * 16 + g;
            #pragma unroll
            for (int nt = 0; nt < 4; nt++) {
                int c0 = nw * 32 + nt * 8 + 2 * q;
                float2 bb = *(const float2*)(b1s + c0);
                uint32_t lo = pack_bf(sp_fast(acc[mt][nt][0] + bb.x), sp_fast(acc[mt][nt][1] + bb.y));
                uint32_t hi = pack_bf(sp_fast(acc[mt][nt][2] + bb.x), sp_fast(acc[mt][nt][3] + bb.y));
                int chunk = c0 >> 3, inner = (c0 & 7) * 2;
                *(uint32_t*)(smc + EA2 + swz2(r, chunk, 256) + inner) = lo;
                *(uint32_t*)(smc + EA2 + swz2(r + 8, chunk, 256) + inner) = hi;
            }
        }
        __syncthreads();

        // ---- GEMM2 ----
        #pragma unroll
        for (int a = 0; a < 2; a++)
            #pragma unroll
            for (int b = 0; b < 4; b++)
                #pragma unroll
                for (int c = 0; c < 4; c++) acc[a][b][c] = 0.f;
        wgemm_sw<128, 256>(A2u, arow, ak, W2u, brow0, bk, acc);

        // ---- dump raw GEMM2 acc into P (f32, xor-swizzled 512B rows) ----
        #pragma unroll
        for (int mt = 0; mt < 2; mt++) {
            int rlo = mw * 32 + mt * 16 + g, rhi = rlo + 8;
            #pragma unroll
            for (int nt = 0; nt < 4; nt++) {
                int c0 = nw * 32 + nt * 8 + 2 * q;
                int chunk = c0 >> 2, inner = (c0 & 3) * 4;
                *(float2*)(smc + EP + (rlo << 9) + (((chunk ^ (rlo & 7)) & 31) << 4) + inner)
                    = make_float2(acc[mt][nt][0], acc[mt][nt][1]);
                *(float2*)(smc + EP + (rhi << 9) + (((chunk ^ (rhi & 7)) & 31) << 4) + inner)
                    = make_float2(acc[mt][nt][2], acc[mt][nt][3]);
            }
        }
        __syncthreads();

        // ---- row pass: full-row coalesced gather-multiply + red.v4 ----
        {
            float4 b2v = *(const float4*)(b2s + lane * 4);
            #pragma unroll
            for (int j = 0; j < 8; j++) {
                int r = wid * 8 + j;
                int e = e0 + r;
                float4 p = *(const float4*)(smc + EP + (r << 9) + (((lane ^ (r & 7)) & 31) << 4));
                float4 xv = xg[j];
                float a0 = sp_fast(p.x + b2v.x) * xv.x;
                float a1 = sp_fast(p.y + b2v.y) * xv.y;
                float a2 = sp_fast(p.z + b2v.z) * xv.z;
                float a3 = sp_fast(p.w + b2v.w) * xv.w;
                if (e < E) {
                    asm volatile("red.global.add.v4.f32 [%0], {%1,%2,%3,%4};"
                                 :: "l"(g_sums + (size_t)n1r[j] * 128 + lane * 4),
                                    "f"(a0), "f"(a1), "f"(a2), "f"(a3) : "memory");
                    if (lane == 0) atomicAdd(&g_cnt[n1r[j]], 1.0f);
                }
            }
        }
        __syncthreads();

        if (have_next) {
            #pragma unroll
            for (int c = 0; c < 4; c++) {
                int ci = c * 256 + tid;
                int m = ci >> 4, qq = ci & 15;
                uint2 pv = {pack_bf(pf[c].x, pf[c].y), pack_bf(pf[c].z, pf[c].w)};
                *(uint2*)(smc + EA1 + swz2(m, qq >> 1, 128) + (qq & 1) * 8) = pv;
            }
            if (tid < 128) {
                if (tid < 64) i1s[tid] = pidx; else i2s[tid - 64] = pidx;
            }
        }
        __syncthreads();
    }
}

// ---------------- Kernel 3: node epilogue (bf16 MMA, persistent) ----------------
#define NODE_SMEM ((128 * 136 * 3) * 2 + 128 * 4 * 3)
__global__ __launch_bounds__(256, 2) void node_mma_kernel(const float* __restrict__ node_fea,
                                                          const float* __restrict__ baw2,
                                                          const float* __restrict__ baw3,
                                                          float* __restrict__ out,
                                                          int N, int ntiles) {
    extern __shared__ char smc[];
    __nv_bfloat16* W2t = (__nv_bfloat16*)smc;
    __nv_bfloat16* W3t = W2t + 128 * 136;
    __nv_bfloat16* As  = W3t + 128 * 136;
    float* inv = (float*)(As + 128 * 136);
    float* b2s = inv + 128;
    float* b3s = b2s + 128;

    int tid = threadIdx.x, wid = tid >> 5, lane = tid & 31;
    int g = lane >> 2, q = lane & 3;
    int mw = wid & 3, nw = wid >> 2;
    int arow = (lane & 7) + ((lane >> 3) & 1) * 8, ak = lane >> 4;
    int brow = (lane & 7) + ((lane >> 4) << 3), bk = (lane >> 3) & 1;

    for (int i = tid; i < 128 * 136 * 2 / 16; i += 256) {
        ((uint4*)W2t)[i] = ((const uint4*)g_wa2b)[i];
        ((uint4*)W3t)[i] = ((const uint4*)g_wa3b)[i];
    }
    if (tid < 128) { b2s[tid] = baw2[tid]; b3s[tid] = baw3[tid]; }

    uint32_t Ab = smem_u32(As) + ((mw * 32 + arow) * 136 + ak * 8) * 2;
    uint32_t B2b = smem_u32(W2t) + ((nw * 64 + brow) * 136 + bk * 8) * 2;
    uint32_t B3b = smem_u32(W3t) + ((nw * 64 + brow) * 136 + bk * 8) * 2;

    for (int t = blockIdx.x; t < ntiles; t += gridDim.x) {
        int r0 = t * 128;
        if (tid < 128) {
            int r = r0 + tid;
            inv[tid] = (r < N) ? 1.f / fmaxf(g_cnt[r], 1.f) : 0.f;
        }
        __syncthreads();
        #pragma unroll
        for (int c = 0; c < 16; c++) {
            int ci = c * 256 + tid;
            int m = ci >> 5, qq = ci & 31;
            int r = r0 + m;
            float4 v = {0.f, 0.f, 0.f, 0.f};
            if (r < N) v = ((const float4*)g_sums)[(size_t)r * 32 + qq];
            float iv = inv[m];
            uint2 pv = {pack_bf(v.x * iv, v.y * iv), pack_bf(v.z * iv, v.w * iv)};
            *(uint2*)((char*)As + (m * 136 + qq * 4) * 2) = pv;
        }
        __syncthreads();

        float acc[2][8][4];
        zero8(acc);
        wgemm<128, 136>(Ab, B2b, acc);

        uint32_t hlo[2][8], hhi[2][8];
        #pragma unroll
        for (int mt = 0; mt < 2; mt++)
            #pragma unroll
            for (int nt = 0; nt < 8; nt++) {
                int c0 = nw * 64 + nt * 8 + 2 * q;
                float2 bb = *(const float2*)(b2s + c0);
                hlo[mt][nt] = pack_bf(sp_fast(acc[mt][nt][0] + bb.x), sp_fast(acc[mt][nt][1] + bb.y));
                hhi[mt][nt] = pack_bf(sp_fast(acc[mt][nt][2] + bb.x), sp_fast(acc[mt][nt][3] + bb.y));
            }
        __syncthreads();
        #pragma unroll
        for (int mt = 0; mt < 2; mt++) {
            int r = mw * 32 + mt * 16 + g;
            #pragma unroll
            for (int nt = 0; nt < 8; nt++) {
                int c0 = nw * 64 + nt * 8 + 2 * q;
                *(uint32_t*)((char*)As + (r * 136 + c0) * 2) = hlo[mt][nt];
                *(uint32_t*)((char*)As + ((r + 8) * 136 + c0) * 2) = hhi[mt][nt];
            }
        }
        __syncthreads();

        zero8(acc);
        wgemm<128, 136>(Ab, B3b, acc);

        #pragma unroll
        for (int mt = 0; mt < 2; mt++) {
            int rlo = r0 + mw * 32 + mt * 16 + g, rhi = rlo + 8;
            #pragma unroll
            for (int nt = 0; nt < 8; nt++) {
                int c0 = nw * 64 + nt * 8 + 2 * q;
                float2 bb = *(const float2*)(b3s + c0);
                if (rlo < N) {
                    float2 nf = *(const float2*)(node_fea + (size_t)rlo * 128 + c0);
                    *(float2*)(out + (size_t)rlo * 128 + c0) =
                        make_float2(nf.x + acc[mt][nt][0] + bb.x, nf.y + acc[mt][nt][1] + bb.y);
                }
                if (rhi < N) {
                    float2 nf = *(const float2*)(node_fea + (size_t)rhi * 128 + c0);
                    *(float2*)(out + (size_t)rhi * 128 + c0) =
                        make_float2(nf.x + acc[mt][nt][2] + bb.x, nf.y + acc[mt][nt][3] + bb.y);
                }
            }
        }
        __syncthreads();
    }
}

extern "C" void kernel_launch(void* const* d_in, const int* in_sizes, int n_in,
                              void* d_out, int out_size) {
    const float* node_fea = (const float*)d_in[0];
    const int*   idx1     = (const int*)d_in[1];
    const int*   idx2     = (const int*)d_in[2];
    const float* edge_fea = (const float*)d_in[3];
    const float* W_aw1    = (const float*)d_in[4];
    const float* W_fg1    = (const float*)d_in[5];
    const float* b_fg1    = (const float*)d_in[6];
    const float* W_fg2    = (const float*)d_in[7];
    const float* b_fg2    = (const float*)d_in[8];
    const float* W_aw2    = (const float*)d_in[9];
    const float* b_aw2    = (const float*)d_in[10];
    const float* W_aw3    = (const float*)d_in[11];
    const float* b_aw3    = (const float*)d_in[12];

    int N = in_sizes[0] / 128;
    int E = in_sizes[1];
    float* out = (float*)d_out;

    void *p_sums, *p_cnt;
    cudaGetSymbolAddress(&p_sums, g_sums);
    cudaGetSymbolAddress(&p_cnt, g_cnt);
    cudaMemsetAsync(p_sums, 0, (size_t)N * 128 * sizeof(float));
    cudaMemsetAsync(p_cnt, 0, (size_t)N * sizeof(float));

    cudaFuncSetAttribute(gemm_x_mma, cudaFuncAttributeMaxDynamicSharedMemorySize, XK_SMEM);
    cudaFuncSetAttribute(edge_mma_kernel, cudaFuncAttributeMaxDynamicSharedMemorySize, EDGE_SMEM);
    cudaFuncSetAttribute(node_mma_kernel, cudaFuncAttributeMaxDynamicSharedMemorySize, NODE_SMEM);

    int ntN = (N + 127) / 128;
    int ntE = (E + 63) / 64;
    int gbN = ntN < 296 ? ntN : 296;
    int gbE = ntE < 296 ? ntE : 296;

    prep_weights<<<64, 256>>>(W_fg1, W_fg2, W_aw1, W_aw2, W_aw3);
    dummy_kernel<<<1, 32>>>();
    gemm_x_mma<<<gbN, 256, XK_SMEM>>>(node_fea, N, ntN);
    edge_mma_kernel<<<gbE, 256, EDGE_SMEM>>>(edge_fea, idx1, idx2, b_fg1, b_fg2, E, ntE);
    node_mma_kernel<<<gbN, 256, NODE_SMEM>>>(node_fea, b_aw2, b_aw3, out, N, ntN);
}